// round 12
// baseline (speedup 1.0000x reference)
#include <cuda_runtime.h>
#include <cuda_bf16.h>
#include <cuda_fp16.h>
#include <cstdint>
#include <math.h>

// Problem constants
#define BB 2
#define SS 2048
#define DD 1024
#define HH 16
#define HD 64
#define MM (BB*SS)
#define NW (DD*DD)

#define NEGBIG (-1e30f)
// 0.125 * log2(e): folds attention scale and base-2 softmax into Q
#define QSCALE 0.1803368801111204f

// ---------------------------------------------------------------------------
// Scratch (no cudaMalloc allowed) — all fp16
// ---------------------------------------------------------------------------
__device__ __half gx_h[MM*DD];
__device__ __half gx_l[MM*DD];
__device__ __half gw_h[4*DD*DD];       // weights: fp16 hi only
__device__ __half gQh[MM*DD];          // (B,H,S,HD) fp16 hi only
__device__ __half gKh[MM*DD];          // K: fp16 hi only
__device__ __half gVh[MM*DD];          // V: fp16 hi only
__device__ __half ga_h[MM*DD];         // attention out (B,S,D) fp16 hi/lo
__device__ __half ga_l[MM*DD];

// ---------------------------------------------------------------------------
// PTX helpers (plain sm_103-safe: mma.sync / ldmatrix / cp.async)
// ---------------------------------------------------------------------------
__device__ __forceinline__ uint32_t smem_u32(const void* p) {
    uint32_t a;
    asm("{ .reg .u64 t; cvta.to.shared.u64 t, %1; cvt.u32.u64 %0, t; }" : "=r"(a) : "l"(p));
    return a;
}

__device__ __forceinline__ void mma_f16(float* c, const uint32_t* a, const uint32_t* b) {
    asm volatile(
        "mma.sync.aligned.m16n8k16.row.col.f32.f16.f16.f32 "
        "{%0,%1,%2,%3}, {%4,%5,%6,%7}, {%8,%9}, {%0,%1,%2,%3};"
        : "+f"(c[0]), "+f"(c[1]), "+f"(c[2]), "+f"(c[3])
        : "r"(a[0]), "r"(a[1]), "r"(a[2]), "r"(a[3]), "r"(b[0]), "r"(b[1]));
}

__device__ __forceinline__ void ldsm4(uint32_t* r, uint32_t addr) {
    asm volatile("ldmatrix.sync.aligned.m8n8.x4.shared.b16 {%0,%1,%2,%3}, [%4];"
        : "=r"(r[0]), "=r"(r[1]), "=r"(r[2]), "=r"(r[3]) : "r"(addr));
}
__device__ __forceinline__ void ldsm4t(uint32_t* r, uint32_t addr) {
    asm volatile("ldmatrix.sync.aligned.m8n8.x4.trans.shared.b16 {%0,%1,%2,%3}, [%4];"
        : "=r"(r[0]), "=r"(r[1]), "=r"(r[2]), "=r"(r[3]) : "r"(addr));
}
__device__ __forceinline__ uint32_t pack_f16(float lo, float hi) {
    uint32_t d;
    asm("cvt.rn.f16x2.f32 %0, %1, %2;" : "=r"(d) : "f"(hi), "f"(lo));
    return d;
}
__device__ __forceinline__ float ex2(float x) {
    float y;
    asm("ex2.approx.f32 %0, %1;" : "=f"(y) : "f"(x));
    return y;
}

#define CP_ASYNC16(dst, src) \
    asm volatile("cp.async.cg.shared.global [%0], [%1], 16;" :: "r"(dst), "l"(src))
#define CP_COMMIT() asm volatile("cp.async.commit_group;" ::: "memory")
#define CP_WAIT2() asm volatile("cp.async.wait_group 2;" ::: "memory")
#define CP_WAIT1() asm volatile("cp.async.wait_group 1;" ::: "memory")
#define CP_WAIT0() asm volatile("cp.async.wait_group 0;" ::: "memory")

extern __shared__ char dsm[];

// ---------------------------------------------------------------------------
// fp32 -> (fp16 hi, fp16 lo) split (x input)
// ---------------------------------------------------------------------------
__global__ __launch_bounds__(256) void split_f16(
    const float* __restrict__ in, __half* __restrict__ hi,
    __half* __restrict__ lo, int n)
{
    int i = (blockIdx.x * 256 + threadIdx.x) * 4;
    if (i >= n) return;
    float4 v = *(const float4*)(in + i);
    __half h0 = __float2half_rn(v.x), h1 = __float2half_rn(v.y);
    __half h2 = __float2half_rn(v.z), h3 = __float2half_rn(v.w);
    __half2 hp0 = __halves2half2(h0, h1), hp1 = __halves2half2(h2, h3);
    __half2 lp0 = __halves2half2(
        __float2half_rn(v.x - __half2float(h0)),
        __float2half_rn(v.y - __half2float(h1)));
    __half2 lp1 = __halves2half2(
        __float2half_rn(v.z - __half2float(h2)),
        __float2half_rn(v.w - __half2float(h3)));
    uint2 hv, lv;
    hv.x = *(uint32_t*)&hp0; hv.y = *(uint32_t*)&hp1;
    lv.x = *(uint32_t*)&lp0; lv.y = *(uint32_t*)&lp1;
    *(uint2*)(hi + i) = hv;
    *(uint2*)(lo + i) = lv;
}

// Fused 4-weight fp32 -> fp16 convert (hi only): blockIdx.y selects tensor
__global__ __launch_bounds__(256) void conv4_f16(
    const float* __restrict__ s0, const float* __restrict__ s1,
    const float* __restrict__ s2, const float* __restrict__ s3,
    __half* __restrict__ hi, int n)
{
    const int t = blockIdx.y;
    const float* s = (t == 0) ? s0 : (t == 1) ? s1 : (t == 2) ? s2 : s3;
    int i = (blockIdx.x * 256 + threadIdx.x) * 4;
    if (i >= n) return;
    float4 v = *(const float4*)(s + i);
    __half2 hp0 = __halves2half2(__float2half_rn(v.x), __float2half_rn(v.y));
    __half2 hp1 = __halves2half2(__float2half_rn(v.z), __float2half_rn(v.w));
    uint2 hv;
    hv.x = *(uint32_t*)&hp0; hv.y = *(uint32_t*)&hp1;
    *(uint2*)(hi + (size_t)t * n + i) = hv;
}

// ---------------------------------------------------------------------------
// fp16 2-term GEMM core: acc = (Ah + Al) . Wh^T   (unchanged from R11)
// 3-stage cp.async pipeline, K-chunk 32, 80B pitch.
// ---------------------------------------------------------------------------
#define PITCH2 80
#define ARR2 (128 * PITCH2)              // 10240
#define STAGE2 (3 * ARR2)                // 30720
#define NSTAGE 3
#define GEMM_SMEM (NSTAGE * STAGE2)      // 92160
#define NK2 (DD / 32)                    // 32 chunks

struct GemmAcc { float a[2][8][4]; };

__device__ __forceinline__ void gemm_mainloop(
    const __half* gA_h, const __half* gA_l, const __half* gW_h,
    int tid, int wm, int wn, GemmAcc& A)
{
    const uint32_t smem_base = smem_u32(dsm);
    const int lane = tid & 31;

    const int r0i = tid >> 2, q0i = tid & 3;
    const uint32_t sdst0 = (uint32_t)(r0i * PITCH2 + q0i * 16);
    const size_t gof0 = (size_t)r0i * DD + q0i * 8;
    const int r1i = (tid + 256) >> 2, q1i = tid & 3;
    const uint32_t sdst1 = (uint32_t)(r1i * PITCH2 + q1i * 16);
    const size_t gof1 = (size_t)r1i * DD + q1i * 8;

    const uint32_t offA = (uint32_t)((lane & 15) * PITCH2 + (lane >> 4) * 16);
    const int m8 = lane >> 3;
    const int radd = lane - ((m8 == 1 || m8 == 2) ? 8 : (m8 == 3 ? 16 : 0));
    const uint32_t offB = (uint32_t)(radd * PITCH2 + ((m8 & 1) ? 16 : 0));

    float (*acc)[8][4] = A.a;
    #pragma unroll
    for (int i = 0; i < 2; i++)
        #pragma unroll
        for (int j = 0; j < 8; j++)
            #pragma unroll
            for (int k = 0; k < 4; k++) acc[i][j][k] = 0.f;

    auto load_chunk = [&](int c) {
        uint32_t st = smem_base + (uint32_t)((c % NSTAGE) * STAGE2);
        size_t g0 = gof0 + (size_t)c * 32;
        size_t g1 = gof1 + (size_t)c * 32;
        CP_ASYNC16(st + 0*ARR2 + sdst0, (const char*)(gA_h + g0));
        CP_ASYNC16(st + 0*ARR2 + sdst1, (const char*)(gA_h + g1));
        CP_ASYNC16(st + 1*ARR2 + sdst0, (const char*)(gA_l + g0));
        CP_ASYNC16(st + 1*ARR2 + sdst1, (const char*)(gA_l + g1));
        CP_ASYNC16(st + 2*ARR2 + sdst0, (const char*)(gW_h + g0));
        CP_ASYNC16(st + 2*ARR2 + sdst1, (const char*)(gW_h + g1));
        CP_COMMIT();
    };

    load_chunk(0);
    load_chunk(1);

    for (int c = 0; c < NK2; c++) {
        if (c + 2 < NK2) {
            load_chunk(c + 2);
            CP_WAIT2();
        } else if (c + 1 < NK2) {
            CP_WAIT1();
        } else {
            CP_WAIT0();
        }
        __syncthreads();

        const uint32_t sb = smem_base + (uint32_t)((c % NSTAGE) * STAGE2);
        const uint32_t aBase = sb + (uint32_t)(wm * 32 * PITCH2) + offA;
        const uint32_t bBase = sb + 2*ARR2 + (uint32_t)(wn * 64 * PITCH2) + offB;

        #pragma unroll
        for (int ks = 0; ks < 2; ks++) {
            const uint32_t ko = (uint32_t)(ks * 32);
            uint32_t aH[2][4], aL[2][4], bb[4][4];
            ldsm4(aH[0], aBase + ko);
            ldsm4(aH[1], aBase + ko + 16 * PITCH2);
            ldsm4(aL[0], aBase + ko + ARR2);
            ldsm4(aL[1], aBase + ko + ARR2 + 16 * PITCH2);
            #pragma unroll
            for (int p = 0; p < 4; p++) ldsm4(bb[p], bBase + ko + p * 16 * PITCH2);

            #pragma unroll
            for (int mt = 0; mt < 2; mt++)
                #pragma unroll
                for (int nt = 0; nt < 8; nt++)
                    mma_f16(acc[mt][nt], aH[mt], &bb[nt >> 1][(nt & 1) * 2]);
            #pragma unroll
            for (int mt = 0; mt < 2; mt++)
                #pragma unroll
                for (int nt = 0; nt < 8; nt++)
                    mma_f16(acc[mt][nt], aL[mt], &bb[nt >> 1][(nt & 1) * 2]);
        }
        __syncthreads();
    }
}

// ---------------------------------------------------------------------------
// Merged QKV GEMM: writes fp16 HI-ONLY outputs in head layout (B,H,S,HD).
// Q pre-scaled by QSCALE.
// ---------------------------------------------------------------------------
__global__ __launch_bounds__(256)
void tc_gemm_qkv(const __half* __restrict__ Ah, const __half* __restrict__ Al,
                 const __half* __restrict__ Wh,
                 const float* __restrict__ bq, const float* __restrict__ bk,
                 const float* __restrict__ bv,
                 __half* __restrict__ Qh, __half* __restrict__ Kh,
                 __half* __restrict__ Vh)
{
    const int tid = threadIdx.x;
    const int wid = tid >> 5, lane = tid & 31;
    const int wm = wid & 3, wn = wid >> 2;
    const int t = blockIdx.x >> 3;
    const int n0 = (blockIdx.x & 7) * 128;
    const int m0 = blockIdx.y * 128;

    const float* bias = (t == 0) ? bq : (t == 1) ? bk : bv;
    __half* outh = (t == 0) ? Qh : (t == 1) ? Kh : Vh;
    const float scale = (t == 0) ? QSCALE : 1.0f;

    GemmAcc A;
    gemm_mainloop(Ah + (size_t)m0 * DD, Al + (size_t)m0 * DD,
                  Wh + (size_t)t * NW + (size_t)n0 * DD,
                  tid, wm, wn, A);

    const int g = lane >> 2, tig = lane & 3;
    #pragma unroll
    for (int mt = 0; mt < 2; mt++) {
        #pragma unroll
        for (int nt = 0; nt < 8; nt++) {
            const int col = n0 + wn * 64 + nt * 8 + tig * 2;
            const float2 b2 = *(const float2*)&bias[col];
            const int r1 = m0 + wm * 32 + mt * 16 + g;
            const int r2 = r1 + 8;
            float v0 = (A.a[mt][nt][0] + b2.x) * scale;
            float v1 = (A.a[mt][nt][1] + b2.y) * scale;
            float v2 = (A.a[mt][nt][2] + b2.x) * scale;
            float v3 = (A.a[mt][nt][3] + b2.y) * scale;
            const int h = col >> 6, hd = col & 63;
            const int b1b = r1 >> 11, s1 = r1 & 2047;
            const int b2b = r2 >> 11, s2 = r2 & 2047;
            size_t i1 = (((size_t)(b1b * HH + h)) * SS + s1) * HD + hd;
            size_t i2 = (((size_t)(b2b * HH + h)) * SS + s2) * HD + hd;
            *(__half2*)&outh[i1] = __halves2half2(__float2half_rn(v0), __float2half_rn(v1));
            *(__half2*)&outh[i2] = __halves2half2(__float2half_rn(v2), __float2half_rn(v3));
        }
    }
}

// ---------------------------------------------------------------------------
// Final projection GEMM: fp32 output (B,S,D); A keeps hi/lo split.
// ---------------------------------------------------------------------------
__global__ __launch_bounds__(256)
void tc_gemm_out(const __half* __restrict__ Ah, const __half* __restrict__ Al,
                 const __half* __restrict__ Wh,
                 const float* __restrict__ bias, float* __restrict__ outf)
{
    const int tid = threadIdx.x;
    const int wid = tid >> 5, lane = tid & 31;
    const int wm = wid & 3, wn = wid >> 2;
    const int n0 = blockIdx.x * 128, m0 = blockIdx.y * 128;

    GemmAcc A;
    gemm_mainloop(Ah + (size_t)m0 * DD, Al + (size_t)m0 * DD,
                  Wh + (size_t)n0 * DD, tid, wm, wn, A);

    const int g = lane >> 2, tig = lane & 3;
    #pragma unroll
    for (int mt = 0; mt < 2; mt++) {
        #pragma unroll
        for (int nt = 0; nt < 8; nt++) {
            const int col = n0 + wn * 64 + nt * 8 + tig * 2;
            const float2 b2 = *(const float2*)&bias[col];
            const int r1 = m0 + wm * 32 + mt * 16 + g;
            const int r2 = r1 + 8;
            float2 w0, w1;
            w0.x = A.a[mt][nt][0] + b2.x; w0.y = A.a[mt][nt][1] + b2.y;
            w1.x = A.a[mt][nt][2] + b2.x; w1.y = A.a[mt][nt][3] + b2.y;
            *(float2*)&outf[(size_t)r1 * DD + col] = w0;
            *(float2*)&outf[(size_t)r2 * DD + col] = w1;
        }
    }
}

// ---------------------------------------------------------------------------
// Flash attention, pure fp16 operands, 1-term MMA each:
//   S = Qh . Kh ; O += fp16(P) . Vh     (64 MMAs per key tile)
// Q pre-scaled by 0.125*log2(e); softmax base 2; interior tiles skip masking.
// smem: stage s at s*ST_SZ: Kh +0 (12288), Vh +12288 (9216).
// Qh staged transiently across both stage regions before the KV loop.
// ---------------------------------------------------------------------------
#define ST_SZ  21504
#define V_OFF  12288
#define SQM_OFF 43008
#define SKM_OFF 43520
#define SQF_OFF 44032
#define SKF_OFF 44048
#define ATT_SMEM 44160

__global__ __launch_bounds__(256, 2) void attn_mma(
    const __half* __restrict__ Qh, const __half* __restrict__ Kh,
    const __half* __restrict__ Vh,
    const int* __restrict__ am,
    __half* __restrict__ Oh, __half* __restrict__ Ol)
{
    const int tid = threadIdx.x, w = tid >> 5, lane = tid & 31;
    const int qt = (int)gridDim.x - 1 - (int)blockIdx.x;   // big tiles first
    const int h = blockIdx.y, b = blockIdx.z;
    const int q0 = qt * 128;
    const int ktmax = 2 * qt + 2;
    const size_t hoff = ((size_t)(b * HH + h)) * SS * HD;
    const __half *qhp = Qh + hoff;
    const __half *khp = Kh + hoff;
    const __half *vhp = Vh + hoff;

    const uint32_t sbase = smem_u32(dsm);
    int* sqm = (int*)(dsm + SQM_OFF);
    int* skm = (int*)(dsm + SKM_OFF);
    int* sqf = (int*)(dsm + SQF_OFF);
    int* skf = (int*)(dsm + SKF_OFF);

    // ---- Q staging (transient, uses stage region; 24576 B < 2*ST_SZ) ----
    #pragma unroll
    for (int i = 0; i < 4; i++) {
        int e = tid + i * 256; int r = e >> 3, c = e & 7;
        uint32_t d = (uint32_t)((c >> 1) * 6144 + r * 48 + (c & 1) * 16);
        CP_ASYNC16(sbase + d, (const char*)(qhp + (size_t)(q0 + r) * HD + c * 8));
    }
    CP_COMMIT();
    if (tid < 128) {
        int v = am[b * SS + q0 + tid];
        sqm[tid] = v;
        unsigned bl = __ballot_sync(0xffffffffu, v != 0);
        if ((tid & 31) == 0) sqf[tid >> 5] = (bl == 0xffffffffu) ? 1 : 0;
    }
    CP_WAIT0();
    __syncthreads();

    const uint32_t offA = (uint32_t)((lane & 15) * 48 + (lane >> 4) * 16);
    const int m8 = lane >> 3;
    const int radd = lane - ((m8 == 1 || m8 == 2) ? 8 : (m8 == 3 ? 16 : 0));
    const uint32_t offB = (uint32_t)(radd * 48 + ((m8 & 1) ? 16 : 0));
    const uint32_t offV = (uint32_t)((((lane & 7) + ((lane >> 3) & 1) * 8)) * 144
                                     + ((lane >> 4) & 1) * 16);

    uint32_t aQh[4][4];
    #pragma unroll
    for (int ks = 0; ks < 4; ks++)
        ldsm4(aQh[ks], sbase + (uint32_t)(ks * 6144 + w * 16 * 48) + offA);
    __syncthreads();   // stage region free for KV now

    auto load_kv = [&](int kt) {
        const int t0 = kt * 64;
        uint32_t st = sbase + (uint32_t)((kt & 1) * ST_SZ);
        #pragma unroll
        for (int i = 0; i < 2; i++) {
            int e = tid + i * 256; int r = e >> 3, c = e & 7;
            size_t g = (size_t)(t0 + r) * HD + c * 8;
            CP_ASYNC16(st + (uint32_t)((c >> 1) * 3072 + r * 48 + (c & 1) * 16),
                       (const char*)(khp + g));
            CP_ASYNC16(st + V_OFF + (uint32_t)(r * 144 + c * 16),
                       (const char*)(vhp + g));
        }
        if (tid < 64) {
            int v = am[b * SS + t0 + tid];
            skm[(kt & 1) * 64 + tid] = v;
            unsigned bl = __ballot_sync(0xffffffffu, v != 0);
            if ((tid & 31) == 0)
                skf[(kt & 1) * 2 + (tid >> 5)] = (bl == 0xffffffffu) ? 1 : 0;
        }
        CP_COMMIT();
    };
    load_kv(0);
    load_kv(1);

    const bool qall = sqf[0] && sqf[1] && sqf[2] && sqf[3];
    const int g = lane >> 2, tig2 = (lane & 3) * 2;
    const int row0 = w * 16 + g;
    const int grow0 = q0 + row0, grow1 = grow0 + 8;
    const bool qok0 = (sqm[row0] != 0), qok1 = (sqm[row0 + 8] != 0);

    float oacc[8][4];
    #pragma unroll
    for (int i = 0; i < 8; i++)
        #pragma unroll
        for (int j = 0; j < 4; j++) oacc[i][j] = 0.f;
    float m0 = NEGBIG, m1 = NEGBIG, l0 = 0.f, l1 = 0.f;

    for (int kt = 0; kt < ktmax; kt++) {
        if (kt + 1 < ktmax) { CP_WAIT1(); } else { CP_WAIT0(); }
        __syncthreads();
        const uint32_t sb = sbase + (uint32_t)((kt & 1) * ST_SZ);
        const int t0 = kt * 64;
        const int* km = skm + (kt & 1) * 64;
        const bool fast = qall && skf[(kt & 1) * 2] && skf[(kt & 1) * 2 + 1]
                          && (t0 + 63 <= q0);

        // ---- S = Qh Kh ----
        float s[8][4];
        #pragma unroll
        for (int i = 0; i < 8; i++)
            #pragma unroll
            for (int j = 0; j < 4; j++) s[i][j] = 0.f;

        #pragma unroll
        for (int ks = 0; ks < 4; ks++) {
            uint32_t kbh[4][4];
            #pragma unroll
            for (int p = 0; p < 4; p++)
                ldsm4(kbh[p], sb + (uint32_t)(ks * 3072 + p * 768) + offB);
            #pragma unroll
            for (int nt = 0; nt < 8; nt++)
                mma_f16(s[nt], aQh[ks], &kbh[nt >> 1][(nt & 1) * 2]);
        }

        // ---- mask (skipped on interior fully-valid tiles) ----
        if (!fast) {
            #pragma unroll
            for (int nt = 0; nt < 8; nt++) {
                int c0 = nt * 8 + tig2;
                int gc0 = t0 + c0, gc1 = gc0 + 1;
                bool k0 = (km[c0] != 0), k1 = (km[c0 + 1] != 0);
                s[nt][0] = (qok0 && k0 && gc0 <= grow0) ? s[nt][0] : NEGBIG;
                s[nt][1] = (qok0 && k1 && gc1 <= grow0) ? s[nt][1] : NEGBIG;
                s[nt][2] = (qok1 && k0 && gc0 <= grow1) ? s[nt][2] : NEGBIG;
                s[nt][3] = (qok1 && k1 && gc1 <= grow1) ? s[nt][3] : NEGBIG;
            }
        }

        // ---- online softmax (base 2) ----
        float mx0 = NEGBIG, mx1 = NEGBIG;
        #pragma unroll
        for (int nt = 0; nt < 8; nt++) {
            mx0 = fmaxf(mx0, fmaxf(s[nt][0], s[nt][1]));
            mx1 = fmaxf(mx1, fmaxf(s[nt][2], s[nt][3]));
        }
        mx0 = fmaxf(mx0, __shfl_xor_sync(0xffffffffu, mx0, 1));
        mx0 = fmaxf(mx0, __shfl_xor_sync(0xffffffffu, mx0, 2));
        mx1 = fmaxf(mx1, __shfl_xor_sync(0xffffffffu, mx1, 1));
        mx1 = fmaxf(mx1, __shfl_xor_sync(0xffffffffu, mx1, 2));
        const float mn0 = fmaxf(m0, mx0), mn1 = fmaxf(m1, mx1);
        const float corr0 = ex2(m0 - mn0), corr1 = ex2(m1 - mn1);
        m0 = mn0; m1 = mn1;
        float sum0 = 0.f, sum1 = 0.f;
        #pragma unroll
        for (int nt = 0; nt < 8; nt++) {
            s[nt][0] = ex2(s[nt][0] - mn0);
            s[nt][1] = ex2(s[nt][1] - mn0);
            s[nt][2] = ex2(s[nt][2] - mn1);
            s[nt][3] = ex2(s[nt][3] - mn1);
            sum0 += s[nt][0] + s[nt][1];
            sum1 += s[nt][2] + s[nt][3];
        }
        sum0 += __shfl_xor_sync(0xffffffffu, sum0, 1);
        sum0 += __shfl_xor_sync(0xffffffffu, sum0, 2);
        sum1 += __shfl_xor_sync(0xffffffffu, sum1, 1);
        sum1 += __shfl_xor_sync(0xffffffffu, sum1, 2);
        l0 = l0 * corr0 + sum0;
        l1 = l1 * corr1 + sum1;
        #pragma unroll
        for (int dt = 0; dt < 8; dt++) {
            oacc[dt][0] *= corr0; oacc[dt][1] *= corr0;
            oacc[dt][2] *= corr1; oacc[dt][3] *= corr1;
        }

        // ---- O += fp16(P) Vh ----
        #pragma unroll
        for (int ts = 0; ts < 4; ts++) {
            uint32_t aP[4];
            aP[0] = pack_f16(s[2*ts][0], s[2*ts][1]);
            aP[1] = pack_f16(s[2*ts][2], s[2*ts][3]);
            aP[2] = pack_f16(s[2*ts+1][0], s[2*ts+1][1]);
            aP[3] = pack_f16(s[2*ts+1][2], s[2*ts+1][3]);

            uint32_t vbh[4][4];
            #pragma unroll
            for (int dp = 0; dp < 4; dp++)
                ldsm4t(vbh[dp], sb + V_OFF + (uint32_t)(ts * 2304 + dp * 32) + offV);
            #pragma unroll
            for (int dt = 0; dt < 8; dt++)
                mma_f16(oacc[dt], aP, &vbh[dt >> 1][(dt & 1) * 2]);
        }
        __syncthreads();
        if (kt + 2 < ktmax) load_kv(kt + 2);
    }

    // ---- epilogue: normalize, hi/lo fp16 to (B,S,D) ----
    const float inv0 = (l0 > 0.f) ? (1.f / l0) : 0.f;
    const float inv1 = (l1 > 0.f) ? (1.f / l1) : 0.f;
    const size_t o0 = ((size_t)(b * SS + grow0)) * DD + h * HD;
    const size_t o1 = ((size_t)(b * SS + grow1)) * DD + h * HD;
    #pragma unroll
    for (int dt = 0; dt < 8; dt++) {
        int dc = dt * 8 + tig2;
        float v0 = oacc[dt][0] * inv0, v1 = oacc[dt][1] * inv0;
        float v2 = oacc[dt][2] * inv1, v3 = oacc[dt][3] * inv1;
        __half h0 = __float2half_rn(v0), h1 = __float2half_rn(v1);
        __half h2 = __float2half_rn(v2), h3 = __float2half_rn(v3);
        *(__half2*)&Oh[o0 + dc] = __halves2half2(h0, h1);
        *(__half2*)&Oh[o1 + dc] = __halves2half2(h2, h3);
        *(__half2*)&Ol[o0 + dc] = __halves2half2(
            __float2half_rn(v0 - __half2float(h0)),
            __float2half_rn(v1 - __half2float(h1)));
        *(__half2*)&Ol[o1 + dc] = __halves2half2(
            __float2half_rn(v2 - __half2float(h2)),
            __float2half_rn(v3 - __half2float(h3)));
    }
}

// ---------------------------------------------------------------------------
extern "C" void kernel_launch(void* const* d_in, const int* in_sizes, int n_in,
                              void* d_out, int out_size)
{
    (void)in_sizes; (void)n_in; (void)out_size;
    const float* x  = (const float*)d_in[0];
    const int*   am = (const int*)d_in[1];
    const float* Wq = (const float*)d_in[2];
    const float* bq = (const float*)d_in[3];
    const float* Wk = (const float*)d_in[4];
    const float* bk = (const float*)d_in[5];
    const float* Wv = (const float*)d_in[6];
    const float* bv = (const float*)d_in[7];
    const float* Wp = (const float*)d_in[8];
    const float* bp = (const float*)d_in[9];
    float* out = (float*)d_out;

    __half *xh, *xl, *wh, *ah, *al;
    __half *qh, *kh, *vh;
    cudaGetSymbolAddress((void**)&xh, gx_h);
    cudaGetSymbolAddress((void**)&xl, gx_l);
    cudaGetSymbolAddress((void**)&wh, gw_h);
    cudaGetSymbolAddress((void**)&ah, ga_h);
    cudaGetSymbolAddress((void**)&al, ga_l);
    cudaGetSymbolAddress((void**)&qh, gQh);
    cudaGetSymbolAddress((void**)&kh, gKh);
    cudaGetSymbolAddress((void**)&vh, gVh);

    cudaFuncSetAttribute(tc_gemm_qkv,
                         cudaFuncAttributeMaxDynamicSharedMemorySize, GEMM_SMEM);
    cudaFuncSetAttribute(tc_gemm_out,
                         cudaFuncAttributeMaxDynamicSharedMemorySize, GEMM_SMEM);
    cudaFuncSetAttribute(attn_mma,
                         cudaFuncAttributeMaxDynamicSharedMemorySize, ATT_SMEM);

    const int NX = MM * DD;

    split_f16<<<NX/1024, 256>>>(x, xh, xl, NX);
    conv4_f16<<<dim3(NW/1024, 4), 256>>>(Wq, Wk, Wv, Wp, wh, NW);

    tc_gemm_qkv<<<dim3(24, MM/128), 256, GEMM_SMEM>>>(
        xh, xl, wh, bq, bk, bv, qh, kh, vh);

    attn_mma<<<dim3(SS/128, HH, BB), 256, ATT_SMEM>>>(qh, kh, vh, am, ah, al);

    tc_gemm_out<<<dim3(DD/128, MM/128), 256, GEMM_SMEM>>>(
        ah, al, wh + 3*NW, bp, out);
}

// round 13
// speedup vs baseline: 1.2616x; 1.2616x over previous
#include <cuda_runtime.h>
#include <cuda_bf16.h>
#include <cuda_fp16.h>
#include <cstdint>
#include <math.h>

// Problem constants
#define BB 2
#define SS 2048
#define DD 1024
#define HH 16
#define HD 64
#define MM (BB*SS)
#define NW (DD*DD)

#define NEGBIG (-1e30f)
// 0.125 * log2(e): folds attention scale and base-2 softmax into Q
#define QSCALE 0.1803368801111204f

// ---------------------------------------------------------------------------
// Scratch (no cudaMalloc allowed) — all fp16
// ---------------------------------------------------------------------------
__device__ __half gx_h[MM*DD];
__device__ __half gx_l[MM*DD];
__device__ __half gw_h[4*DD*DD];       // weights: fp16 hi only
__device__ __half gQh[MM*DD];          // (B,H,S,HD) fp16 hi/lo
__device__ __half gQl[MM*DD];
__device__ __half gKh[MM*DD];          // K: fp16 hi only
__device__ __half gVh[MM*DD];
__device__ __half gVl[MM*DD];
__device__ __half ga_h[MM*DD];         // attention out (B,S,D) fp16 hi/lo
__device__ __half ga_l[MM*DD];

// ---------------------------------------------------------------------------
// PTX helpers (plain sm_103-safe: mma.sync / ldmatrix / cp.async)
// ---------------------------------------------------------------------------
__device__ __forceinline__ uint32_t smem_u32(const void* p) {
    uint32_t a;
    asm("{ .reg .u64 t; cvta.to.shared.u64 t, %1; cvt.u32.u64 %0, t; }" : "=r"(a) : "l"(p));
    return a;
}

__device__ __forceinline__ void mma_f16(float* c, const uint32_t* a, const uint32_t* b) {
    asm volatile(
        "mma.sync.aligned.m16n8k16.row.col.f32.f16.f16.f32 "
        "{%0,%1,%2,%3}, {%4,%5,%6,%7}, {%8,%9}, {%0,%1,%2,%3};"
        : "+f"(c[0]), "+f"(c[1]), "+f"(c[2]), "+f"(c[3])
        : "r"(a[0]), "r"(a[1]), "r"(a[2]), "r"(a[3]), "r"(b[0]), "r"(b[1]));
}

__device__ __forceinline__ void ldsm4(uint32_t* r, uint32_t addr) {
    asm volatile("ldmatrix.sync.aligned.m8n8.x4.shared.b16 {%0,%1,%2,%3}, [%4];"
        : "=r"(r[0]), "=r"(r[1]), "=r"(r[2]), "=r"(r[3]) : "r"(addr));
}
__device__ __forceinline__ void ldsm4t(uint32_t* r, uint32_t addr) {
    asm volatile("ldmatrix.sync.aligned.m8n8.x4.trans.shared.b16 {%0,%1,%2,%3}, [%4];"
        : "=r"(r[0]), "=r"(r[1]), "=r"(r[2]), "=r"(r[3]) : "r"(addr));
}
__device__ __forceinline__ uint32_t pack_f16(float lo, float hi) {
    uint32_t d;
    asm("cvt.rn.f16x2.f32 %0, %1, %2;" : "=r"(d) : "f"(hi), "f"(lo));
    return d;
}
__device__ __forceinline__ float ex2(float x) {
    float y;
    asm("ex2.approx.f32 %0, %1;" : "=f"(y) : "f"(x));
    return y;
}

#define CP_ASYNC16(dst, src) \
    asm volatile("cp.async.cg.shared.global [%0], [%1], 16;" :: "r"(dst), "l"(src))
#define CP_COMMIT() asm volatile("cp.async.commit_group;" ::: "memory")
#define CP_WAIT2() asm volatile("cp.async.wait_group 2;" ::: "memory")
#define CP_WAIT1() asm volatile("cp.async.wait_group 1;" ::: "memory")
#define CP_WAIT0() asm volatile("cp.async.wait_group 0;" ::: "memory")

extern __shared__ char dsm[];

// ---------------------------------------------------------------------------
// Fused fp32 -> fp16 conversion for all 5 tensors, one launch.
// blockIdx.y == 0: x -> hi+lo split.  1..4: weight t-1 -> hi only.
// ---------------------------------------------------------------------------
__global__ __launch_bounds__(256) void conv_all(
    const float* __restrict__ x,
    const float* __restrict__ w0, const float* __restrict__ w1,
    const float* __restrict__ w2, const float* __restrict__ w3,
    __half* __restrict__ xhi, __half* __restrict__ xlo,
    __half* __restrict__ whi)
{
    const int t = blockIdx.y;
    int i = (blockIdx.x * 256 + threadIdx.x) * 4;
    if (t == 0) {
        if (i >= MM * DD) return;
        float4 v = *(const float4*)(x + i);
        __half h0 = __float2half_rn(v.x), h1 = __float2half_rn(v.y);
        __half h2 = __float2half_rn(v.z), h3 = __float2half_rn(v.w);
        __half2 hp0 = __halves2half2(h0, h1), hp1 = __halves2half2(h2, h3);
        __half2 lp0 = __halves2half2(
            __float2half_rn(v.x - __half2float(h0)),
            __float2half_rn(v.y - __half2float(h1)));
        __half2 lp1 = __halves2half2(
            __float2half_rn(v.z - __half2float(h2)),
            __float2half_rn(v.w - __half2float(h3)));
        uint2 hv, lv;
        hv.x = *(uint32_t*)&hp0; hv.y = *(uint32_t*)&hp1;
        lv.x = *(uint32_t*)&lp0; lv.y = *(uint32_t*)&lp1;
        *(uint2*)(xhi + i) = hv;
        *(uint2*)(xlo + i) = lv;
    } else {
        if (i >= NW) return;
        const float* s = (t == 1) ? w0 : (t == 2) ? w1 : (t == 3) ? w2 : w3;
        float4 v = *(const float4*)(s + i);
        __half2 hp0 = __halves2half2(__float2half_rn(v.x), __float2half_rn(v.y));
        __half2 hp1 = __halves2half2(__float2half_rn(v.z), __float2half_rn(v.w));
        uint2 hv;
        hv.x = *(uint32_t*)&hp0; hv.y = *(uint32_t*)&hp1;
        *(uint2*)(whi + (size_t)(t - 1) * NW + i) = hv;
    }
}

// ---------------------------------------------------------------------------
// fp16 2-term GEMM core: acc = (Ah + Al) . Wh^T   (R11-proven)
// 3-stage cp.async pipeline, K-chunk 32, 80B pitch.
// ---------------------------------------------------------------------------
#define PITCH2 80
#define ARR2 (128 * PITCH2)              // 10240
#define STAGE2 (3 * ARR2)                // 30720
#define NSTAGE 3
#define GEMM_SMEM (NSTAGE * STAGE2)      // 92160
#define NK2 (DD / 32)                    // 32 chunks

struct GemmAcc { float a[2][8][4]; };

__device__ __forceinline__ void gemm_mainloop(
    const __half* gA_h, const __half* gA_l, const __half* gW_h,
    int tid, int wm, int wn, GemmAcc& A)
{
    const uint32_t smem_base = smem_u32(dsm);
    const int lane = tid & 31;

    const int r0i = tid >> 2, q0i = tid & 3;
    const uint32_t sdst0 = (uint32_t)(r0i * PITCH2 + q0i * 16);
    const size_t gof0 = (size_t)r0i * DD + q0i * 8;
    const int r1i = (tid + 256) >> 2, q1i = tid & 3;
    const uint32_t sdst1 = (uint32_t)(r1i * PITCH2 + q1i * 16);
    const size_t gof1 = (size_t)r1i * DD + q1i * 8;

    const uint32_t offA = (uint32_t)((lane & 15) * PITCH2 + (lane >> 4) * 16);
    const int m8 = lane >> 3;
    const int radd = lane - ((m8 == 1 || m8 == 2) ? 8 : (m8 == 3 ? 16 : 0));
    const uint32_t offB = (uint32_t)(radd * PITCH2 + ((m8 & 1) ? 16 : 0));

    float (*acc)[8][4] = A.a;
    #pragma unroll
    for (int i = 0; i < 2; i++)
        #pragma unroll
        for (int j = 0; j < 8; j++)
            #pragma unroll
            for (int k = 0; k < 4; k++) acc[i][j][k] = 0.f;

    auto load_chunk = [&](int c) {
        uint32_t st = smem_base + (uint32_t)((c % NSTAGE) * STAGE2);
        size_t g0 = gof0 + (size_t)c * 32;
        size_t g1 = gof1 + (size_t)c * 32;
        CP_ASYNC16(st + 0*ARR2 + sdst0, (const char*)(gA_h + g0));
        CP_ASYNC16(st + 0*ARR2 + sdst1, (const char*)(gA_h + g1));
        CP_ASYNC16(st + 1*ARR2 + sdst0, (const char*)(gA_l + g0));
        CP_ASYNC16(st + 1*ARR2 + sdst1, (const char*)(gA_l + g1));
        CP_ASYNC16(st + 2*ARR2 + sdst0, (const char*)(gW_h + g0));
        CP_ASYNC16(st + 2*ARR2 + sdst1, (const char*)(gW_h + g1));
        CP_COMMIT();
    };

    load_chunk(0);
    load_chunk(1);

    for (int c = 0; c < NK2; c++) {
        if (c + 2 < NK2) {
            load_chunk(c + 2);
            CP_WAIT2();
        } else if (c + 1 < NK2) {
            CP_WAIT1();
        } else {
            CP_WAIT0();
        }
        __syncthreads();

        const uint32_t sb = smem_base + (uint32_t)((c % NSTAGE) * STAGE2);
        const uint32_t aBase = sb + (uint32_t)(wm * 32 * PITCH2) + offA;
        const uint32_t bBase = sb + 2*ARR2 + (uint32_t)(wn * 64 * PITCH2) + offB;

        #pragma unroll
        for (int ks = 0; ks < 2; ks++) {
            const uint32_t ko = (uint32_t)(ks * 32);
            uint32_t aH[2][4], aL[2][4], bb[4][4];
            ldsm4(aH[0], aBase + ko);
            ldsm4(aH[1], aBase + ko + 16 * PITCH2);
            ldsm4(aL[0], aBase + ko + ARR2);
            ldsm4(aL[1], aBase + ko + ARR2 + 16 * PITCH2);
            #pragma unroll
            for (int p = 0; p < 4; p++) ldsm4(bb[p], bBase + ko + p * 16 * PITCH2);

            #pragma unroll
            for (int mt = 0; mt < 2; mt++)
                #pragma unroll
                for (int nt = 0; nt < 8; nt++)
                    mma_f16(acc[mt][nt], aH[mt], &bb[nt >> 1][(nt & 1) * 2]);
            #pragma unroll
            for (int mt = 0; mt < 2; mt++)
                #pragma unroll
                for (int nt = 0; nt < 8; nt++)
                    mma_f16(acc[mt][nt], aL[mt], &bb[nt >> 1][(nt & 1) * 2]);
        }
        __syncthreads();
    }
}

// ---------------------------------------------------------------------------
// Merged QKV GEMM: writes fp16 outputs in head layout (B,H,S,HD).
// Q: hi+lo fp16 (pre-scaled by QSCALE); K: hi only; V: hi+lo.
// ---------------------------------------------------------------------------
__global__ __launch_bounds__(256)
void tc_gemm_qkv(const __half* __restrict__ Ah, const __half* __restrict__ Al,
                 const __half* __restrict__ Wh,
                 const float* __restrict__ bq, const float* __restrict__ bk,
                 const float* __restrict__ bv,
                 __half* __restrict__ Qh, __half* __restrict__ Ql,
                 __half* __restrict__ Kh,
                 __half* __restrict__ Vh, __half* __restrict__ Vl)
{
    const int tid = threadIdx.x;
    const int wid = tid >> 5, lane = tid & 31;
    const int wm = wid & 3, wn = wid >> 2;
    const int t = blockIdx.x >> 3;
    const int n0 = (blockIdx.x & 7) * 128;
    const int m0 = blockIdx.y * 128;

    const float* bias = (t == 0) ? bq : (t == 1) ? bk : bv;
    __half* outh = (t == 0) ? Qh : (t == 1) ? Kh : Vh;
    __half* outl = (t == 0) ? Ql : Vl;   // unused for t==1
    const float scale = (t == 0) ? QSCALE : 1.0f;

    GemmAcc A;
    gemm_mainloop(Ah + (size_t)m0 * DD, Al + (size_t)m0 * DD,
                  Wh + (size_t)t * NW + (size_t)n0 * DD,
                  tid, wm, wn, A);

    const int g = lane >> 2, tig = lane & 3;
    #pragma unroll
    for (int mt = 0; mt < 2; mt++) {
        #pragma unroll
        for (int nt = 0; nt < 8; nt++) {
            const int col = n0 + wn * 64 + nt * 8 + tig * 2;
            const float2 b2 = *(const float2*)&bias[col];
            const int r1 = m0 + wm * 32 + mt * 16 + g;
            const int r2 = r1 + 8;
            float v0 = (A.a[mt][nt][0] + b2.x) * scale;
            float v1 = (A.a[mt][nt][1] + b2.y) * scale;
            float v2 = (A.a[mt][nt][2] + b2.x) * scale;
            float v3 = (A.a[mt][nt][3] + b2.y) * scale;
            const int h = col >> 6, hd = col & 63;
            const int b1b = r1 >> 11, s1 = r1 & 2047;
            const int b2b = r2 >> 11, s2 = r2 & 2047;
            size_t i1 = (((size_t)(b1b * HH + h)) * SS + s1) * HD + hd;
            size_t i2 = (((size_t)(b2b * HH + h)) * SS + s2) * HD + hd;
            __half h0 = __float2half_rn(v0), h1 = __float2half_rn(v1);
            __half h2 = __float2half_rn(v2), h3 = __float2half_rn(v3);
            *(__half2*)&outh[i1] = __halves2half2(h0, h1);
            *(__half2*)&outh[i2] = __halves2half2(h2, h3);
            if (t != 1) {
                __half l0 = __float2half_rn(v0 - __half2float(h0));
                __half l1 = __float2half_rn(v1 - __half2float(h1));
                __half l2 = __float2half_rn(v2 - __half2float(h2));
                __half l3 = __float2half_rn(v3 - __half2float(h3));
                *(__half2*)&outl[i1] = __halves2half2(l0, l1);
                *(__half2*)&outl[i2] = __halves2half2(l2, l3);
            }
        }
    }
}

// ---------------------------------------------------------------------------
// Final projection GEMM: fp32 output (B,S,D)
// ---------------------------------------------------------------------------
__global__ __launch_bounds__(256)
void tc_gemm_out(const __half* __restrict__ Ah, const __half* __restrict__ Al,
                 const __half* __restrict__ Wh,
                 const float* __restrict__ bias, float* __restrict__ outf)
{
    const int tid = threadIdx.x;
    const int wid = tid >> 5, lane = tid & 31;
    const int wm = wid & 3, wn = wid >> 2;
    const int n0 = blockIdx.x * 128, m0 = blockIdx.y * 128;

    GemmAcc A;
    gemm_mainloop(Ah + (size_t)m0 * DD, Al + (size_t)m0 * DD,
                  Wh + (size_t)n0 * DD, tid, wm, wn, A);

    const int g = lane >> 2, tig = lane & 3;
    #pragma unroll
    for (int mt = 0; mt < 2; mt++) {
        #pragma unroll
        for (int nt = 0; nt < 8; nt++) {
            const int col = n0 + wn * 64 + nt * 8 + tig * 2;
            const float2 b2 = *(const float2*)&bias[col];
            const int r1 = m0 + wm * 32 + mt * 16 + g;
            const int r2 = r1 + 8;
            float2 w0, w1;
            w0.x = A.a[mt][nt][0] + b2.x; w0.y = A.a[mt][nt][1] + b2.y;
            w1.x = A.a[mt][nt][2] + b2.x; w1.y = A.a[mt][nt][3] + b2.y;
            *(float2*)&outf[(size_t)r1 * DD + col] = w0;
            *(float2*)&outf[(size_t)r2 * DD + col] = w1;
        }
    }
}

// ---------------------------------------------------------------------------
// Flash attention, fp16 operands (R11 mainloop):
//   S = (Qh + Ql) . Kh ; O += fp16(P) . (Vh + Vl)
// ---------------------------------------------------------------------------
#define QL_OFF 0
#define ST_OFF 24576
#define ST_SZ  30720
#define V_OFF  12288
#define SQM_OFF 86016
#define SKM_OFF 86528
#define SQF_OFF 87040
#define SKF_OFF 87056
#define ATT_SMEM 87168

__global__ __launch_bounds__(256, 2) void attn_mma(
    const __half* __restrict__ Qh, const __half* __restrict__ Ql,
    const __half* __restrict__ Kh,
    const __half* __restrict__ Vh, const __half* __restrict__ Vl,
    const int* __restrict__ am,
    __half* __restrict__ Oh, __half* __restrict__ Ol)
{
    const int tid = threadIdx.x, w = tid >> 5, lane = tid & 31;
    const int qt = (int)gridDim.x - 1 - (int)blockIdx.x;   // big tiles first
    const int h = blockIdx.y, b = blockIdx.z;
    const int q0 = qt * 128;
    const int ktmax = 2 * qt + 2;
    const size_t hoff = ((size_t)(b * HH + h)) * SS * HD;
    const __half *qhp = Qh + hoff, *qlp = Ql + hoff;
    const __half *khp = Kh + hoff;
    const __half *vhp = Vh + hoff, *vlp = Vl + hoff;

    const uint32_t sbase = smem_u32(dsm);
    int* sqm = (int*)(dsm + SQM_OFF);
    int* skm = (int*)(dsm + SKM_OFF);
    int* sqf = (int*)(dsm + SQF_OFF);
    int* skf = (int*)(dsm + SKF_OFF);

    // ---- Q staging: Ql persistent at 0, Qh transient at ST_OFF ----
    #pragma unroll
    for (int i = 0; i < 4; i++) {
        int e = tid + i * 256; int r = e >> 3, c = e & 7;
        uint32_t d = (uint32_t)((c >> 1) * 6144 + r * 48 + (c & 1) * 16);
        const size_t g = (size_t)(q0 + r) * HD + c * 8;
        CP_ASYNC16(sbase + QL_OFF + d, (const char*)(qlp + g));
        CP_ASYNC16(sbase + ST_OFF + d, (const char*)(qhp + g));
    }
    CP_COMMIT();
    if (tid < 128) {
        int v = am[b * SS + q0 + tid];
        sqm[tid] = v;
        unsigned bl = __ballot_sync(0xffffffffu, v != 0);
        if ((tid & 31) == 0) sqf[tid >> 5] = (bl == 0xffffffffu) ? 1 : 0;
    }
    CP_WAIT0();
    __syncthreads();

    const uint32_t offA = (uint32_t)((lane & 15) * 48 + (lane >> 4) * 16);
    const int m8 = lane >> 3;
    const int radd = lane - ((m8 == 1 || m8 == 2) ? 8 : (m8 == 3 ? 16 : 0));
    const uint32_t offB = (uint32_t)(radd * 48 + ((m8 & 1) ? 16 : 0));
    const uint32_t offV = (uint32_t)((((lane & 7) + ((lane >> 3) & 1) * 8)) * 144
                                     + ((lane >> 4) & 1) * 16);

    uint32_t aQh[4][4];
    #pragma unroll
    for (int ks = 0; ks < 4; ks++)
        ldsm4(aQh[ks], sbase + ST_OFF + (uint32_t)(ks * 6144 + w * 16 * 48) + offA);
    __syncthreads();   // Qh region free for KV stages now

    auto load_kv = [&](int kt) {
        const int t0 = kt * 64;
        uint32_t st = sbase + ST_OFF + (uint32_t)((kt & 1) * ST_SZ);
        #pragma unroll
        for (int i = 0; i < 2; i++) {
            int e = tid + i * 256; int r = e >> 3, c = e & 7;
            size_t g = (size_t)(t0 + r) * HD + c * 8;
            uint32_t kd = st + (uint32_t)((c >> 1) * 3072 + r * 48 + (c & 1) * 16);
            CP_ASYNC16(kd, (const char*)(khp + g));
            uint32_t vd = st + V_OFF + (uint32_t)(r * 144 + c * 16);
            CP_ASYNC16(vd, (const char*)(vhp + g));
            CP_ASYNC16(vd + 9216, (const char*)(vlp + g));
        }
        if (tid < 64) {
            int v = am[b * SS + t0 + tid];
            skm[(kt & 1) * 64 + tid] = v;
            unsigned bl = __ballot_sync(0xffffffffu, v != 0);
            if ((tid & 31) == 0)
                skf[(kt & 1) * 2 + (tid >> 5)] = (bl == 0xffffffffu) ? 1 : 0;
        }
        CP_COMMIT();
    };
    load_kv(0);
    load_kv(1);

    const bool qall = sqf[0] && sqf[1] && sqf[2] && sqf[3];
    const int g = lane >> 2, tig2 = (lane & 3) * 2;
    const int row0 = w * 16 + g;
    const int grow0 = q0 + row0, grow1 = grow0 + 8;
    const bool qok0 = (sqm[row0] != 0), qok1 = (sqm[row0 + 8] != 0);

    float oacc[8][4];
    #pragma unroll
    for (int i = 0; i < 8; i++)
        #pragma unroll
        for (int j = 0; j < 4; j++) oacc[i][j] = 0.f;
    float m0 = NEGBIG, m1 = NEGBIG, l0 = 0.f, l1 = 0.f;

    for (int kt = 0; kt < ktmax; kt++) {
        if (kt + 1 < ktmax) { CP_WAIT1(); } else { CP_WAIT0(); }
        __syncthreads();
        const uint32_t sb = sbase + ST_OFF + (uint32_t)((kt & 1) * ST_SZ);
        const int t0 = kt * 64;
        const int* km = skm + (kt & 1) * 64;
        const bool fast = qall && skf[(kt & 1) * 2] && skf[(kt & 1) * 2 + 1]
                          && (t0 + 63 <= q0);

        // ---- S = (Qh + Ql) Kh ----
        float s[8][4];
        #pragma unroll
        for (int i = 0; i < 8; i++)
            #pragma unroll
            for (int j = 0; j < 4; j++) s[i][j] = 0.f;

        #pragma unroll
        for (int ks = 0; ks < 4; ks++) {
            uint32_t aQl_t[4];
            ldsm4(aQl_t, sbase + QL_OFF + (uint32_t)(ks * 6144 + w * 16 * 48) + offA);
            uint32_t kbh[4][4];
            #pragma unroll
            for (int p = 0; p < 4; p++)
                ldsm4(kbh[p], sb + (uint32_t)(ks * 3072 + p * 768) + offB);
            #pragma unroll
            for (int nt = 0; nt < 8; nt++) {
                mma_f16(s[nt], aQh[ks], &kbh[nt >> 1][(nt & 1) * 2]);
                mma_f16(s[nt], aQl_t, &kbh[nt >> 1][(nt & 1) * 2]);
            }
        }

        // ---- mask (skipped on interior fully-valid tiles) ----
        if (!fast) {
            #pragma unroll
            for (int nt = 0; nt < 8; nt++) {
                int c0 = nt * 8 + tig2;
                int gc0 = t0 + c0, gc1 = gc0 + 1;
                bool k0 = (km[c0] != 0), k1 = (km[c0 + 1] != 0);
                s[nt][0] = (qok0 && k0 && gc0 <= grow0) ? s[nt][0] : NEGBIG;
                s[nt][1] = (qok0 && k1 && gc1 <= grow0) ? s[nt][1] : NEGBIG;
                s[nt][2] = (qok1 && k0 && gc0 <= grow1) ? s[nt][2] : NEGBIG;
                s[nt][3] = (qok1 && k1 && gc1 <= grow1) ? s[nt][3] : NEGBIG;
            }
        }

        // ---- online softmax (base 2) ----
        float mx0 = NEGBIG, mx1 = NEGBIG;
        #pragma unroll
        for (int nt = 0; nt < 8; nt++) {
            mx0 = fmaxf(mx0, fmaxf(s[nt][0], s[nt][1]));
            mx1 = fmaxf(mx1, fmaxf(s[nt][2], s[nt][3]));
        }
        mx0 = fmaxf(mx0, __shfl_xor_sync(0xffffffffu, mx0, 1));
        mx0 = fmaxf(mx0, __shfl_xor_sync(0xffffffffu, mx0, 2));
        mx1 = fmaxf(mx1, __shfl_xor_sync(0xffffffffu, mx1, 1));
        mx1 = fmaxf(mx1, __shfl_xor_sync(0xffffffffu, mx1, 2));
        const float mn0 = fmaxf(m0, mx0), mn1 = fmaxf(m1, mx1);
        const float corr0 = ex2(m0 - mn0), corr1 = ex2(m1 - mn1);
        m0 = mn0; m1 = mn1;
        float sum0 = 0.f, sum1 = 0.f;
        #pragma unroll
        for (int nt = 0; nt < 8; nt++) {
            s[nt][0] = ex2(s[nt][0] - mn0);
            s[nt][1] = ex2(s[nt][1] - mn0);
            s[nt][2] = ex2(s[nt][2] - mn1);
            s[nt][3] = ex2(s[nt][3] - mn1);
            sum0 += s[nt][0] + s[nt][1];
            sum1 += s[nt][2] + s[nt][3];
        }
        sum0 += __shfl_xor_sync(0xffffffffu, sum0, 1);
        sum0 += __shfl_xor_sync(0xffffffffu, sum0, 2);
        sum1 += __shfl_xor_sync(0xffffffffu, sum1, 1);
        sum1 += __shfl_xor_sync(0xffffffffu, sum1, 2);
        l0 = l0 * corr0 + sum0;
        l1 = l1 * corr1 + sum1;
        #pragma unroll
        for (int dt = 0; dt < 8; dt++) {
            oacc[dt][0] *= corr0; oacc[dt][1] *= corr0;
            oacc[dt][2] *= corr1; oacc[dt][3] *= corr1;
        }

        // ---- O += fp16(P) (Vh + Vl) ----
        #pragma unroll
        for (int ts = 0; ts < 4; ts++) {
            uint32_t aP[4];
            aP[0] = pack_f16(s[2*ts][0], s[2*ts][1]);
            aP[1] = pack_f16(s[2*ts][2], s[2*ts][3]);
            aP[2] = pack_f16(s[2*ts+1][0], s[2*ts+1][1]);
            aP[3] = pack_f16(s[2*ts+1][2], s[2*ts+1][3]);

            uint32_t vbh[4][4], vbl[4][4];
            #pragma unroll
            for (int dp = 0; dp < 4; dp++) {
                uint32_t va = sb + V_OFF + (uint32_t)(ts * 2304 + dp * 32) + offV;
                ldsm4t(vbh[dp], va);
                ldsm4t(vbl[dp], va + 9216);
            }
            #pragma unroll
            for (int dt = 0; dt < 8; dt++) {
                mma_f16(oacc[dt], aP, &vbh[dt >> 1][(dt & 1) * 2]);
                mma_f16(oacc[dt], aP, &vbl[dt >> 1][(dt & 1) * 2]);
            }
        }
        __syncthreads();
        if (kt + 2 < ktmax) load_kv(kt + 2);
    }

    // ---- epilogue: normalize, hi/lo fp16 to (B,S,D) ----
    const float inv0 = (l0 > 0.f) ? (1.f / l0) : 0.f;
    const float inv1 = (l1 > 0.f) ? (1.f / l1) : 0.f;
    const size_t o0 = ((size_t)(b * SS + grow0)) * DD + h * HD;
    const size_t o1 = ((size_t)(b * SS + grow1)) * DD + h * HD;
    #pragma unroll
    for (int dt = 0; dt < 8; dt++) {
        int dc = dt * 8 + tig2;
        float v0 = oacc[dt][0] * inv0, v1 = oacc[dt][1] * inv0;
        float v2 = oacc[dt][2] * inv1, v3 = oacc[dt][3] * inv1;
        __half h0 = __float2half_rn(v0), h1 = __float2half_rn(v1);
        __half h2 = __float2half_rn(v2), h3 = __float2half_rn(v3);
        *(__half2*)&Oh[o0 + dc] = __halves2half2(h0, h1);
        *(__half2*)&Oh[o1 + dc] = __halves2half2(h2, h3);
        *(__half2*)&Ol[o0 + dc] = __halves2half2(
            __float2half_rn(v0 - __half2float(h0)),
            __float2half_rn(v1 - __half2float(h1)));
        *(__half2*)&Ol[o1 + dc] = __halves2half2(
            __float2half_rn(v2 - __half2float(h2)),
            __float2half_rn(v3 - __half2float(h3)));
    }
}

// ---------------------------------------------------------------------------
extern "C" void kernel_launch(void* const* d_in, const int* in_sizes, int n_in,
                              void* d_out, int out_size)
{
    (void)in_sizes; (void)n_in; (void)out_size;
    const float* x  = (const float*)d_in[0];
    const int*   am = (const int*)d_in[1];
    const float* Wq = (const float*)d_in[2];
    const float* bq = (const float*)d_in[3];
    const float* Wk = (const float*)d_in[4];
    const float* bk = (const float*)d_in[5];
    const float* Wv = (const float*)d_in[6];
    const float* bv = (const float*)d_in[7];
    const float* Wp = (const float*)d_in[8];
    const float* bp = (const float*)d_in[9];
    float* out = (float*)d_out;

    __half *xh, *xl, *wh, *ah, *al;
    __half *qh, *ql, *kh, *vh, *vl;
    cudaGetSymbolAddress((void**)&xh, gx_h);
    cudaGetSymbolAddress((void**)&xl, gx_l);
    cudaGetSymbolAddress((void**)&wh, gw_h);
    cudaGetSymbolAddress((void**)&ah, ga_h);
    cudaGetSymbolAddress((void**)&al, ga_l);
    cudaGetSymbolAddress((void**)&qh, gQh);
    cudaGetSymbolAddress((void**)&ql, gQl);
    cudaGetSymbolAddress((void**)&kh, gKh);
    cudaGetSymbolAddress((void**)&vh, gVh);
    cudaGetSymbolAddress((void**)&vl, gVl);

    cudaFuncSetAttribute(tc_gemm_qkv,
                         cudaFuncAttributeMaxDynamicSharedMemorySize, GEMM_SMEM);
    cudaFuncSetAttribute(tc_gemm_out,
                         cudaFuncAttributeMaxDynamicSharedMemorySize, GEMM_SMEM);
    cudaFuncSetAttribute(attn_mma,
                         cudaFuncAttributeMaxDynamicSharedMemorySize, ATT_SMEM);

    // Fused conversion: grid.x sized for the larger tensor (x, 4M elems).
    conv_all<<<dim3(MM*DD/1024, 5), 256>>>(x, Wq, Wk, Wv, Wp, xh, xl, wh);

    tc_gemm_qkv<<<dim3(24, MM/128), 256, GEMM_SMEM>>>(
        xh, xl, wh, bq, bk, bv, qh, ql, kh, vh, vl);

    attn_mma<<<dim3(SS/128, HH, BB), 256, ATT_SMEM>>>(qh, ql, kh, vh, vl,
                                                      am, ah, al);

    tc_gemm_out<<<dim3(DD/128, MM/128), 256, GEMM_SMEM>>>(
        ah, al, wh + 3*NW, bp, out);
}

// round 14
// speedup vs baseline: 1.3007x; 1.0310x over previous
#include <cuda_runtime.h>
#include <cuda_bf16.h>
#include <cuda_fp16.h>
#include <cstdint>
#include <math.h>

// Problem constants
#define BB 2
#define SS 2048
#define DD 1024
#define HH 16
#define HD 64
#define MM (BB*SS)
#define NW (DD*DD)

#define NEGBIG (-1e30f)
// 0.125 * log2(e): folds attention scale and base-2 softmax into Q
#define QSCALE 0.1803368801111204f

// ---------------------------------------------------------------------------
// Scratch (no cudaMalloc allowed) — all fp16
// ---------------------------------------------------------------------------
__device__ __half gx_h[MM*DD];
__device__ __half gx_l[MM*DD];
__device__ __half gw_h[4*DD*DD];       // weights: fp16 hi only
__device__ __half gQh[MM*DD];          // (B,H,S,HD) fp16 hi/lo
__device__ __half gQl[MM*DD];
__device__ __half gKh[MM*DD];          // K: fp16 hi only
__device__ __half gVh[MM*DD];
__device__ __half gVl[MM*DD];
__device__ __half ga_h[MM*DD];         // attention out (B,S,D) fp16 hi/lo
__device__ __half ga_l[MM*DD];

// ---------------------------------------------------------------------------
// PTX helpers (plain sm_103-safe: mma.sync / ldmatrix / cp.async)
// ---------------------------------------------------------------------------
__device__ __forceinline__ uint32_t smem_u32(const void* p) {
    uint32_t a;
    asm("{ .reg .u64 t; cvta.to.shared.u64 t, %1; cvt.u32.u64 %0, t; }" : "=r"(a) : "l"(p));
    return a;
}

__device__ __forceinline__ void mma_f16(float* c, const uint32_t* a, const uint32_t* b) {
    asm volatile(
        "mma.sync.aligned.m16n8k16.row.col.f32.f16.f16.f32 "
        "{%0,%1,%2,%3}, {%4,%5,%6,%7}, {%8,%9}, {%0,%1,%2,%3};"
        : "+f"(c[0]), "+f"(c[1]), "+f"(c[2]), "+f"(c[3])
        : "r"(a[0]), "r"(a[1]), "r"(a[2]), "r"(a[3]), "r"(b[0]), "r"(b[1]));
}

__device__ __forceinline__ void ldsm4(uint32_t* r, uint32_t addr) {
    asm volatile("ldmatrix.sync.aligned.m8n8.x4.shared.b16 {%0,%1,%2,%3}, [%4];"
        : "=r"(r[0]), "=r"(r[1]), "=r"(r[2]), "=r"(r[3]) : "r"(addr));
}
__device__ __forceinline__ void ldsm4t(uint32_t* r, uint32_t addr) {
    asm volatile("ldmatrix.sync.aligned.m8n8.x4.trans.shared.b16 {%0,%1,%2,%3}, [%4];"
        : "=r"(r[0]), "=r"(r[1]), "=r"(r[2]), "=r"(r[3]) : "r"(addr));
}
__device__ __forceinline__ uint32_t pack_f16(float lo, float hi) {
    uint32_t d;
    asm("cvt.rn.f16x2.f32 %0, %1, %2;" : "=r"(d) : "f"(hi), "f"(lo));
    return d;
}
__device__ __forceinline__ float ex2(float x) {
    float y;
    asm("ex2.approx.f32 %0, %1;" : "=f"(y) : "f"(x));
    return y;
}

#define CP_ASYNC16(dst, src) \
    asm volatile("cp.async.cg.shared.global [%0], [%1], 16;" :: "r"(dst), "l"(src))
#define CP_COMMIT() asm volatile("cp.async.commit_group;" ::: "memory")
#define CP_WAIT2() asm volatile("cp.async.wait_group 2;" ::: "memory")
#define CP_WAIT1() asm volatile("cp.async.wait_group 1;" ::: "memory")
#define CP_WAIT0() asm volatile("cp.async.wait_group 0;" ::: "memory")

extern __shared__ char dsm[];

// ---------------------------------------------------------------------------
// fp32 -> (fp16 hi, fp16 lo) split (x input)
// ---------------------------------------------------------------------------
__global__ __launch_bounds__(256) void split_f16(
    const float* __restrict__ in, __half* __restrict__ hi,
    __half* __restrict__ lo, int n)
{
    int i = (blockIdx.x * 256 + threadIdx.x) * 4;
    if (i >= n) return;
    float4 v = *(const float4*)(in + i);
    __half h0 = __float2half_rn(v.x), h1 = __float2half_rn(v.y);
    __half h2 = __float2half_rn(v.z), h3 = __float2half_rn(v.w);
    __half2 hp0 = __halves2half2(h0, h1), hp1 = __halves2half2(h2, h3);
    __half2 lp0 = __halves2half2(
        __float2half_rn(v.x - __half2float(h0)),
        __float2half_rn(v.y - __half2float(h1)));
    __half2 lp1 = __halves2half2(
        __float2half_rn(v.z - __half2float(h2)),
        __float2half_rn(v.w - __half2float(h3)));
    uint2 hv, lv;
    hv.x = *(uint32_t*)&hp0; hv.y = *(uint32_t*)&hp1;
    lv.x = *(uint32_t*)&lp0; lv.y = *(uint32_t*)&lp1;
    *(uint2*)(hi + i) = hv;
    *(uint2*)(lo + i) = lv;
}

// Fused 4-weight fp32 -> fp16 convert (hi only): blockIdx.y selects tensor
__global__ __launch_bounds__(256) void conv4_f16(
    const float* __restrict__ s0, const float* __restrict__ s1,
    const float* __restrict__ s2, const float* __restrict__ s3,
    __half* __restrict__ hi, int n)
{
    const int t = blockIdx.y;
    const float* s = (t == 0) ? s0 : (t == 1) ? s1 : (t == 2) ? s2 : s3;
    int i = (blockIdx.x * 256 + threadIdx.x) * 4;
    if (i >= n) return;
    float4 v = *(const float4*)(s + i);
    __half2 hp0 = __halves2half2(__float2half_rn(v.x), __float2half_rn(v.y));
    __half2 hp1 = __halves2half2(__float2half_rn(v.z), __float2half_rn(v.w));
    uint2 hv;
    hv.x = *(uint32_t*)&hp0; hv.y = *(uint32_t*)&hp1;
    *(uint2*)(hi + (size_t)t * n + i) = hv;
}

// ---------------------------------------------------------------------------
// fp16 2-term GEMM core: acc = (Ah + Al) . Wh^T   (R11-proven)
// 3-stage cp.async pipeline, K-chunk 32, 80B pitch.
// ---------------------------------------------------------------------------
#define PITCH2 80
#define ARR2 (128 * PITCH2)              // 10240
#define STAGE2 (3 * ARR2)                // 30720
#define NSTAGE 3
#define GEMM_SMEM (NSTAGE * STAGE2)      // 92160
#define NK2 (DD / 32)                    // 32 chunks

struct GemmAcc { float a[2][8][4]; };

__device__ __forceinline__ void gemm_mainloop(
    const __half* gA_h, const __half* gA_l, const __half* gW_h,
    int tid, int wm, int wn, GemmAcc& A)
{
    const uint32_t smem_base = smem_u32(dsm);
    const int lane = tid & 31;

    const int r0i = tid >> 2, q0i = tid & 3;
    const uint32_t sdst0 = (uint32_t)(r0i * PITCH2 + q0i * 16);
    const size_t gof0 = (size_t)r0i * DD + q0i * 8;
    const int r1i = (tid + 256) >> 2, q1i = tid & 3;
    const uint32_t sdst1 = (uint32_t)(r1i * PITCH2 + q1i * 16);
    const size_t gof1 = (size_t)r1i * DD + q1i * 8;

    const uint32_t offA = (uint32_t)((lane & 15) * PITCH2 + (lane >> 4) * 16);
    const int m8 = lane >> 3;
    const int radd = lane - ((m8 == 1 || m8 == 2) ? 8 : (m8 == 3 ? 16 : 0));
    const uint32_t offB = (uint32_t)(radd * PITCH2 + ((m8 & 1) ? 16 : 0));

    float (*acc)[8][4] = A.a;
    #pragma unroll
    for (int i = 0; i < 2; i++)
        #pragma unroll
        for (int j = 0; j < 8; j++)
            #pragma unroll
            for (int k = 0; k < 4; k++) acc[i][j][k] = 0.f;

    auto load_chunk = [&](int c) {
        uint32_t st = smem_base + (uint32_t)((c % NSTAGE) * STAGE2);
        size_t g0 = gof0 + (size_t)c * 32;
        size_t g1 = gof1 + (size_t)c * 32;
        CP_ASYNC16(st + 0*ARR2 + sdst0, (const char*)(gA_h + g0));
        CP_ASYNC16(st + 0*ARR2 + sdst1, (const char*)(gA_h + g1));
        CP_ASYNC16(st + 1*ARR2 + sdst0, (const char*)(gA_l + g0));
        CP_ASYNC16(st + 1*ARR2 + sdst1, (const char*)(gA_l + g1));
        CP_ASYNC16(st + 2*ARR2 + sdst0, (const char*)(gW_h + g0));
        CP_ASYNC16(st + 2*ARR2 + sdst1, (const char*)(gW_h + g1));
        CP_COMMIT();
    };

    load_chunk(0);
    load_chunk(1);

    for (int c = 0; c < NK2; c++) {
        if (c + 2 < NK2) {
            load_chunk(c + 2);
            CP_WAIT2();
        } else if (c + 1 < NK2) {
            CP_WAIT1();
        } else {
            CP_WAIT0();
        }
        __syncthreads();

        const uint32_t sb = smem_base + (uint32_t)((c % NSTAGE) * STAGE2);
        const uint32_t aBase = sb + (uint32_t)(wm * 32 * PITCH2) + offA;
        const uint32_t bBase = sb + 2*ARR2 + (uint32_t)(wn * 64 * PITCH2) + offB;

        #pragma unroll
        for (int ks = 0; ks < 2; ks++) {
            const uint32_t ko = (uint32_t)(ks * 32);
            uint32_t aH[2][4], aL[2][4], bb[4][4];
            ldsm4(aH[0], aBase + ko);
            ldsm4(aH[1], aBase + ko + 16 * PITCH2);
            ldsm4(aL[0], aBase + ko + ARR2);
            ldsm4(aL[1], aBase + ko + ARR2 + 16 * PITCH2);
            #pragma unroll
            for (int p = 0; p < 4; p++) ldsm4(bb[p], bBase + ko + p * 16 * PITCH2);

            #pragma unroll
            for (int mt = 0; mt < 2; mt++)
                #pragma unroll
                for (int nt = 0; nt < 8; nt++)
                    mma_f16(acc[mt][nt], aH[mt], &bb[nt >> 1][(nt & 1) * 2]);
            #pragma unroll
            for (int mt = 0; mt < 2; mt++)
                #pragma unroll
                for (int nt = 0; nt < 8; nt++)
                    mma_f16(acc[mt][nt], aL[mt], &bb[nt >> 1][(nt & 1) * 2]);
        }
        __syncthreads();
    }
}

// ---------------------------------------------------------------------------
// Merged QKV GEMM: writes fp16 outputs in head layout (B,H,S,HD).
// Q: hi+lo fp16 (pre-scaled by QSCALE); K: hi only; V: hi+lo.
// ---------------------------------------------------------------------------
__global__ __launch_bounds__(256)
void tc_gemm_qkv(const __half* __restrict__ Ah, const __half* __restrict__ Al,
                 const __half* __restrict__ Wh,
                 const float* __restrict__ bq, const float* __restrict__ bk,
                 const float* __restrict__ bv,
                 __half* __restrict__ Qh, __half* __restrict__ Ql,
                 __half* __restrict__ Kh,
                 __half* __restrict__ Vh, __half* __restrict__ Vl)
{
    const int tid = threadIdx.x;
    const int wid = tid >> 5, lane = tid & 31;
    const int wm = wid & 3, wn = wid >> 2;
    const int t = blockIdx.x >> 3;
    const int n0 = (blockIdx.x & 7) * 128;
    const int m0 = blockIdx.y * 128;

    const float* bias = (t == 0) ? bq : (t == 1) ? bk : bv;
    __half* outh = (t == 0) ? Qh : (t == 1) ? Kh : Vh;
    __half* outl = (t == 0) ? Ql : Vl;   // unused for t==1
    const float scale = (t == 0) ? QSCALE : 1.0f;

    GemmAcc A;
    gemm_mainloop(Ah + (size_t)m0 * DD, Al + (size_t)m0 * DD,
                  Wh + (size_t)t * NW + (size_t)n0 * DD,
                  tid, wm, wn, A);

    const int g = lane >> 2, tig = lane & 3;
    #pragma unroll
    for (int mt = 0; mt < 2; mt++) {
        #pragma unroll
        for (int nt = 0; nt < 8; nt++) {
            const int col = n0 + wn * 64 + nt * 8 + tig * 2;
            const float2 b2 = *(const float2*)&bias[col];
            const int r1 = m0 + wm * 32 + mt * 16 + g;
            const int r2 = r1 + 8;
            float v0 = (A.a[mt][nt][0] + b2.x) * scale;
            float v1 = (A.a[mt][nt][1] + b2.y) * scale;
            float v2 = (A.a[mt][nt][2] + b2.x) * scale;
            float v3 = (A.a[mt][nt][3] + b2.y) * scale;
            const int h = col >> 6, hd = col & 63;
            const int b1b = r1 >> 11, s1 = r1 & 2047;
            const int b2b = r2 >> 11, s2 = r2 & 2047;
            size_t i1 = (((size_t)(b1b * HH + h)) * SS + s1) * HD + hd;
            size_t i2 = (((size_t)(b2b * HH + h)) * SS + s2) * HD + hd;
            __half h0 = __float2half_rn(v0), h1 = __float2half_rn(v1);
            __half h2 = __float2half_rn(v2), h3 = __float2half_rn(v3);
            *(__half2*)&outh[i1] = __halves2half2(h0, h1);
            *(__half2*)&outh[i2] = __halves2half2(h2, h3);
            if (t != 1) {
                __half l0 = __float2half_rn(v0 - __half2float(h0));
                __half l1 = __float2half_rn(v1 - __half2float(h1));
                __half l2 = __float2half_rn(v2 - __half2float(h2));
                __half l3 = __float2half_rn(v3 - __half2float(h3));
                *(__half2*)&outl[i1] = __halves2half2(l0, l1);
                *(__half2*)&outl[i2] = __halves2half2(l2, l3);
            }
        }
    }
}

// ---------------------------------------------------------------------------
// Final projection GEMM: fp32 output (B,S,D)
// ---------------------------------------------------------------------------
__global__ __launch_bounds__(256)
void tc_gemm_out(const __half* __restrict__ Ah, const __half* __restrict__ Al,
                 const __half* __restrict__ Wh,
                 const float* __restrict__ bias, float* __restrict__ outf)
{
    const int tid = threadIdx.x;
    const int wid = tid >> 5, lane = tid & 31;
    const int wm = wid & 3, wn = wid >> 2;
    const int n0 = blockIdx.x * 128, m0 = blockIdx.y * 128;

    GemmAcc A;
    gemm_mainloop(Ah + (size_t)m0 * DD, Al + (size_t)m0 * DD,
                  Wh + (size_t)n0 * DD, tid, wm, wn, A);

    const int g = lane >> 2, tig = lane & 3;
    #pragma unroll
    for (int mt = 0; mt < 2; mt++) {
        #pragma unroll
        for (int nt = 0; nt < 8; nt++) {
            const int col = n0 + wn * 64 + nt * 8 + tig * 2;
            const float2 b2 = *(const float2*)&bias[col];
            const int r1 = m0 + wm * 32 + mt * 16 + g;
            const int r2 = r1 + 8;
            float2 w0, w1;
            w0.x = A.a[mt][nt][0] + b2.x; w0.y = A.a[mt][nt][1] + b2.y;
            w1.x = A.a[mt][nt][2] + b2.x; w1.y = A.a[mt][nt][3] + b2.y;
            *(float2*)&outf[(size_t)r1 * DD + col] = w0;
            *(float2*)&outf[(size_t)r2 * DD + col] = w1;
        }
    }
}

// ---------------------------------------------------------------------------
// Flash attention, fp16 operands (R11 mainloop), with DEFERRED l-reduction:
//   S = (Qh + Ql) . Kh ; O += fp16(P) . (Vh + Vl)
// Per-tile cross-thread sum shuffles removed; l kept as per-thread partials
// rescaled by corr each tile, reduced once in the epilogue.
// ---------------------------------------------------------------------------
#define QL_OFF 0
#define ST_OFF 24576
#define ST_SZ  30720
#define V_OFF  12288
#define SQM_OFF 86016
#define SKM_OFF 86528
#define SQF_OFF 87040
#define SKF_OFF 87056
#define ATT_SMEM 87168

__global__ __launch_bounds__(256, 2) void attn_mma(
    const __half* __restrict__ Qh, const __half* __restrict__ Ql,
    const __half* __restrict__ Kh,
    const __half* __restrict__ Vh, const __half* __restrict__ Vl,
    const int* __restrict__ am,
    __half* __restrict__ Oh, __half* __restrict__ Ol)
{
    const int tid = threadIdx.x, w = tid >> 5, lane = tid & 31;
    const int qt = (int)gridDim.x - 1 - (int)blockIdx.x;   // big tiles first
    const int h = blockIdx.y, b = blockIdx.z;
    const int q0 = qt * 128;
    const int ktmax = 2 * qt + 2;
    const size_t hoff = ((size_t)(b * HH + h)) * SS * HD;
    const __half *qhp = Qh + hoff, *qlp = Ql + hoff;
    const __half *khp = Kh + hoff;
    const __half *vhp = Vh + hoff, *vlp = Vl + hoff;

    const uint32_t sbase = smem_u32(dsm);
    int* sqm = (int*)(dsm + SQM_OFF);
    int* skm = (int*)(dsm + SKM_OFF);
    int* sqf = (int*)(dsm + SQF_OFF);
    int* skf = (int*)(dsm + SKF_OFF);

    // ---- Q staging: Ql persistent at 0, Qh transient at ST_OFF ----
    #pragma unroll
    for (int i = 0; i < 4; i++) {
        int e = tid + i * 256; int r = e >> 3, c = e & 7;
        uint32_t d = (uint32_t)((c >> 1) * 6144 + r * 48 + (c & 1) * 16);
        const size_t g = (size_t)(q0 + r) * HD + c * 8;
        CP_ASYNC16(sbase + QL_OFF + d, (const char*)(qlp + g));
        CP_ASYNC16(sbase + ST_OFF + d, (const char*)(qhp + g));
    }
    CP_COMMIT();
    if (tid < 128) {
        int v = am[b * SS + q0 + tid];
        sqm[tid] = v;
        unsigned bl = __ballot_sync(0xffffffffu, v != 0);
        if ((tid & 31) == 0) sqf[tid >> 5] = (bl == 0xffffffffu) ? 1 : 0;
    }
    CP_WAIT0();
    __syncthreads();

    const uint32_t offA = (uint32_t)((lane & 15) * 48 + (lane >> 4) * 16);
    const int m8 = lane >> 3;
    const int radd = lane - ((m8 == 1 || m8 == 2) ? 8 : (m8 == 3 ? 16 : 0));
    const uint32_t offB = (uint32_t)(radd * 48 + ((m8 & 1) ? 16 : 0));
    const uint32_t offV = (uint32_t)((((lane & 7) + ((lane >> 3) & 1) * 8)) * 144
                                     + ((lane >> 4) & 1) * 16);

    uint32_t aQh[4][4];
    #pragma unroll
    for (int ks = 0; ks < 4; ks++)
        ldsm4(aQh[ks], sbase + ST_OFF + (uint32_t)(ks * 6144 + w * 16 * 48) + offA);
    __syncthreads();   // Qh region free for KV stages now

    auto load_kv = [&](int kt) {
        const int t0 = kt * 64;
        uint32_t st = sbase + ST_OFF + (uint32_t)((kt & 1) * ST_SZ);
        #pragma unroll
        for (int i = 0; i < 2; i++) {
            int e = tid + i * 256; int r = e >> 3, c = e & 7;
            size_t g = (size_t)(t0 + r) * HD + c * 8;
            uint32_t kd = st + (uint32_t)((c >> 1) * 3072 + r * 48 + (c & 1) * 16);
            CP_ASYNC16(kd, (const char*)(khp + g));
            uint32_t vd = st + V_OFF + (uint32_t)(r * 144 + c * 16);
            CP_ASYNC16(vd, (const char*)(vhp + g));
            CP_ASYNC16(vd + 9216, (const char*)(vlp + g));
        }
        if (tid < 64) {
            int v = am[b * SS + t0 + tid];
            skm[(kt & 1) * 64 + tid] = v;
            unsigned bl = __ballot_sync(0xffffffffu, v != 0);
            if ((tid & 31) == 0)
                skf[(kt & 1) * 2 + (tid >> 5)] = (bl == 0xffffffffu) ? 1 : 0;
        }
        CP_COMMIT();
    };
    load_kv(0);
    load_kv(1);

    const bool qall = sqf[0] && sqf[1] && sqf[2] && sqf[3];
    const int g = lane >> 2, tig2 = (lane & 3) * 2;
    const int row0 = w * 16 + g;
    const int grow0 = q0 + row0, grow1 = grow0 + 8;
    const bool qok0 = (sqm[row0] != 0), qok1 = (sqm[row0 + 8] != 0);

    float oacc[8][4];
    #pragma unroll
    for (int i = 0; i < 8; i++)
        #pragma unroll
        for (int j = 0; j < 4; j++) oacc[i][j] = 0.f;
    float m0 = NEGBIG, m1 = NEGBIG;
    float l0p = 0.f, l1p = 0.f;        // per-thread partial sums (deferred reduce)

    for (int kt = 0; kt < ktmax; kt++) {
        if (kt + 1 < ktmax) { CP_WAIT1(); } else { CP_WAIT0(); }
        __syncthreads();
        const uint32_t sb = sbase + ST_OFF + (uint32_t)((kt & 1) * ST_SZ);
        const int t0 = kt * 64;
        const int* km = skm + (kt & 1) * 64;
        const bool fast = qall && skf[(kt & 1) * 2] && skf[(kt & 1) * 2 + 1]
                          && (t0 + 63 <= q0);

        // ---- S = (Qh + Ql) Kh ----
        float s[8][4];
        #pragma unroll
        for (int i = 0; i < 8; i++)
            #pragma unroll
            for (int j = 0; j < 4; j++) s[i][j] = 0.f;

        #pragma unroll
        for (int ks = 0; ks < 4; ks++) {
            uint32_t aQl_t[4];
            ldsm4(aQl_t, sbase + QL_OFF + (uint32_t)(ks * 6144 + w * 16 * 48) + offA);
            uint32_t kbh[4][4];
            #pragma unroll
            for (int p = 0; p < 4; p++)
                ldsm4(kbh[p], sb + (uint32_t)(ks * 3072 + p * 768) + offB);
            #pragma unroll
            for (int nt = 0; nt < 8; nt++) {
                mma_f16(s[nt], aQh[ks], &kbh[nt >> 1][(nt & 1) * 2]);
                mma_f16(s[nt], aQl_t, &kbh[nt >> 1][(nt & 1) * 2]);
            }
        }

        // ---- mask (skipped on interior fully-valid tiles) ----
        if (!fast) {
            #pragma unroll
            for (int nt = 0; nt < 8; nt++) {
                int c0 = nt * 8 + tig2;
                int gc0 = t0 + c0, gc1 = gc0 + 1;
                bool k0 = (km[c0] != 0), k1 = (km[c0 + 1] != 0);
                s[nt][0] = (qok0 && k0 && gc0 <= grow0) ? s[nt][0] : NEGBIG;
                s[nt][1] = (qok0 && k1 && gc1 <= grow0) ? s[nt][1] : NEGBIG;
                s[nt][2] = (qok1 && k0 && gc0 <= grow1) ? s[nt][2] : NEGBIG;
                s[nt][3] = (qok1 && k1 && gc1 <= grow1) ? s[nt][3] : NEGBIG;
            }
        }

        // ---- online softmax (base 2; max reduce only, sum deferred) ----
        float mx0 = NEGBIG, mx1 = NEGBIG;
        #pragma unroll
        for (int nt = 0; nt < 8; nt++) {
            mx0 = fmaxf(mx0, fmaxf(s[nt][0], s[nt][1]));
            mx1 = fmaxf(mx1, fmaxf(s[nt][2], s[nt][3]));
        }
        mx0 = fmaxf(mx0, __shfl_xor_sync(0xffffffffu, mx0, 1));
        mx0 = fmaxf(mx0, __shfl_xor_sync(0xffffffffu, mx0, 2));
        mx1 = fmaxf(mx1, __shfl_xor_sync(0xffffffffu, mx1, 1));
        mx1 = fmaxf(mx1, __shfl_xor_sync(0xffffffffu, mx1, 2));
        const float mn0 = fmaxf(m0, mx0), mn1 = fmaxf(m1, mx1);
        const float corr0 = ex2(m0 - mn0), corr1 = ex2(m1 - mn1);
        m0 = mn0; m1 = mn1;
        float sum0 = 0.f, sum1 = 0.f;
        #pragma unroll
        for (int nt = 0; nt < 8; nt++) {
            s[nt][0] = ex2(s[nt][0] - mn0);
            s[nt][1] = ex2(s[nt][1] - mn0);
            s[nt][2] = ex2(s[nt][2] - mn1);
            s[nt][3] = ex2(s[nt][3] - mn1);
            sum0 += s[nt][0] + s[nt][1];
            sum1 += s[nt][2] + s[nt][3];
        }
        l0p = l0p * corr0 + sum0;       // no shuffles here
        l1p = l1p * corr1 + sum1;
        #pragma unroll
        for (int dt = 0; dt < 8; dt++) {
            oacc[dt][0] *= corr0; oacc[dt][1] *= corr0;
            oacc[dt][2] *= corr1; oacc[dt][3] *= corr1;
        }

        // ---- O += fp16(P) (Vh + Vl) ----
        #pragma unroll
        for (int ts = 0; ts < 4; ts++) {
            uint32_t aP[4];
            aP[0] = pack_f16(s[2*ts][0], s[2*ts][1]);
            aP[1] = pack_f16(s[2*ts][2], s[2*ts][3]);
            aP[2] = pack_f16(s[2*ts+1][0], s[2*ts+1][1]);
            aP[3] = pack_f16(s[2*ts+1][2], s[2*ts+1][3]);

            uint32_t vbh[4][4], vbl[4][4];
            #pragma unroll
            for (int dp = 0; dp < 4; dp++) {
                uint32_t va = sb + V_OFF + (uint32_t)(ts * 2304 + dp * 32) + offV;
                ldsm4t(vbh[dp], va);
                ldsm4t(vbl[dp], va + 9216);
            }
            #pragma unroll
            for (int dt = 0; dt < 8; dt++) {
                mma_f16(oacc[dt], aP, &vbh[dt >> 1][(dt & 1) * 2]);
                mma_f16(oacc[dt], aP, &vbl[dt >> 1][(dt & 1) * 2]);
            }
        }
        __syncthreads();
        if (kt + 2 < ktmax) load_kv(kt + 2);
    }

    // ---- epilogue: reduce l partials once, normalize, hi/lo fp16 ----
    float l0 = l0p, l1 = l1p;
    l0 += __shfl_xor_sync(0xffffffffu, l0, 1);
    l0 += __shfl_xor_sync(0xffffffffu, l0, 2);
    l1 += __shfl_xor_sync(0xffffffffu, l1, 1);
    l1 += __shfl_xor_sync(0xffffffffu, l1, 2);
    const float inv0 = (l0 > 0.f) ? (1.f / l0) : 0.f;
    const float inv1 = (l1 > 0.f) ? (1.f / l1) : 0.f;
    const size_t o0 = ((size_t)(b * SS + grow0)) * DD + h * HD;
    const size_t o1 = ((size_t)(b * SS + grow1)) * DD + h * HD;
    #pragma unroll
    for (int dt = 0; dt < 8; dt++) {
        int dc = dt * 8 + tig2;
        float v0 = oacc[dt][0] * inv0, v1 = oacc[dt][1] * inv0;
        float v2 = oacc[dt][2] * inv1, v3 = oacc[dt][3] * inv1;
        __half h0 = __float2half_rn(v0), h1 = __float2half_rn(v1);
        __half h2 = __float2half_rn(v2), h3 = __float2half_rn(v3);
        *(__half2*)&Oh[o0 + dc] = __halves2half2(h0, h1);
        *(__half2*)&Oh[o1 + dc] = __halves2half2(h2, h3);
        *(__half2*)&Ol[o0 + dc] = __halves2half2(
            __float2half_rn(v0 - __half2float(h0)),
            __float2half_rn(v1 - __half2float(h1)));
        *(__half2*)&Ol[o1 + dc] = __halves2half2(
            __float2half_rn(v2 - __half2float(h2)),
            __float2half_rn(v3 - __half2float(h3)));
    }
}

// ---------------------------------------------------------------------------
extern "C" void kernel_launch(void* const* d_in, const int* in_sizes, int n_in,
                              void* d_out, int out_size)
{
    (void)in_sizes; (void)n_in; (void)out_size;
    const float* x  = (const float*)d_in[0];
    const int*   am = (const int*)d_in[1];
    const float* Wq = (const float*)d_in[2];
    const float* bq = (const float*)d_in[3];
    const float* Wk = (const float*)d_in[4];
    const float* bk = (const float*)d_in[5];
    const float* Wv = (const float*)d_in[6];
    const float* bv = (const float*)d_in[7];
    const float* Wp = (const float*)d_in[8];
    const float* bp = (const float*)d_in[9];
    float* out = (float*)d_out;

    __half *xh, *xl, *wh, *ah, *al;
    __half *qh, *ql, *kh, *vh, *vl;
    cudaGetSymbolAddress((void**)&xh, gx_h);
    cudaGetSymbolAddress((void**)&xl, gx_l);
    cudaGetSymbolAddress((void**)&wh, gw_h);
    cudaGetSymbolAddress((void**)&ah, ga_h);
    cudaGetSymbolAddress((void**)&al, ga_l);
    cudaGetSymbolAddress((void**)&qh, gQh);
    cudaGetSymbolAddress((void**)&ql, gQl);
    cudaGetSymbolAddress((void**)&kh, gKh);
    cudaGetSymbolAddress((void**)&vh, gVh);
    cudaGetSymbolAddress((void**)&vl, gVl);

    cudaFuncSetAttribute(tc_gemm_qkv,
                         cudaFuncAttributeMaxDynamicSharedMemorySize, GEMM_SMEM);
    cudaFuncSetAttribute(tc_gemm_out,
                         cudaFuncAttributeMaxDynamicSharedMemorySize, GEMM_SMEM);
    cudaFuncSetAttribute(attn_mma,
                         cudaFuncAttributeMaxDynamicSharedMemorySize, ATT_SMEM);

    const int NX = MM * DD;

    split_f16<<<NX/1024, 256>>>(x, xh, xl, NX);
    conv4_f16<<<dim3(NW/1024, 4), 256>>>(Wq, Wk, Wv, Wp, wh, NW);

    tc_gemm_qkv<<<dim3(24, MM/128), 256, GEMM_SMEM>>>(
        xh, xl, wh, bq, bk, bv, qh, ql, kh, vh, vl);

    attn_mma<<<dim3(SS/128, HH, BB), 256, ATT_SMEM>>>(qh, ql, kh, vh, vl,
                                                      am, ah, al);

    tc_gemm_out<<<dim3(DD/128, MM/128), 256, GEMM_SMEM>>>(
        ah, al, wh + 3*NW, bp, out);
}

// round 16
// speedup vs baseline: 1.3593x; 1.0450x over previous
#include <cuda_runtime.h>
#include <cuda_bf16.h>
#include <cuda_fp16.h>
#include <cstdint>
#include <math.h>

// Problem constants
#define BB 2
#define SS 2048
#define DD 1024
#define HH 16
#define HD 64
#define MM (BB*SS)
#define NW (DD*DD)

#define NEGBIG (-1e30f)
// 0.125 * log2(e): folds attention scale and base-2 softmax into Q
#define QSCALE 0.1803368801111204f

// ---------------------------------------------------------------------------
// Scratch (no cudaMalloc allowed) — all fp16
// ---------------------------------------------------------------------------
__device__ __half gx_h[MM*DD];
__device__ __half gx_l[MM*DD];
__device__ __half gw_h[4*DD*DD];       // weights: fp16 hi only
__device__ __half gQh[MM*DD];          // (B,H,S,HD) fp16 hi/lo
__device__ __half gQl[MM*DD];
__device__ __half gKh[MM*DD];          // K: fp16 hi only
__device__ __half gVh[MM*DD];
__device__ __half gVl[MM*DD];
__device__ __half ga_h[MM*DD];         // attention out (B,S,D) fp16 hi/lo
__device__ __half ga_l[MM*DD];
__device__ uint32_t g_km[512 * 3 * 2]; // per-CTA key-mask ballot words

// ---------------------------------------------------------------------------
// PTX helpers (plain sm_103-safe: mma.sync / ldmatrix / cp.async)
// ---------------------------------------------------------------------------
__device__ __forceinline__ uint32_t smem_u32(const void* p) {
    uint32_t a;
    asm("{ .reg .u64 t; cvta.to.shared.u64 t, %1; cvt.u32.u64 %0, t; }" : "=r"(a) : "l"(p));
    return a;
}

__device__ __forceinline__ void mma_f16(float* c, const uint32_t* a, const uint32_t* b) {
    asm volatile(
        "mma.sync.aligned.m16n8k16.row.col.f32.f16.f16.f32 "
        "{%0,%1,%2,%3}, {%4,%5,%6,%7}, {%8,%9}, {%0,%1,%2,%3};"
        : "+f"(c[0]), "+f"(c[1]), "+f"(c[2]), "+f"(c[3])
        : "r"(a[0]), "r"(a[1]), "r"(a[2]), "r"(a[3]), "r"(b[0]), "r"(b[1]));
}

__device__ __forceinline__ void ldsm4(uint32_t* r, uint32_t addr) {
    asm volatile("ldmatrix.sync.aligned.m8n8.x4.shared.b16 {%0,%1,%2,%3}, [%4];"
        : "=r"(r[0]), "=r"(r[1]), "=r"(r[2]), "=r"(r[3]) : "r"(addr));
}
__device__ __forceinline__ void ldsm4t(uint32_t* r, uint32_t addr) {
    asm volatile("ldmatrix.sync.aligned.m8n8.x4.trans.shared.b16 {%0,%1,%2,%3}, [%4];"
        : "=r"(r[0]), "=r"(r[1]), "=r"(r[2]), "=r"(r[3]) : "r"(addr));
}
__device__ __forceinline__ uint32_t pack_f16(float lo, float hi) {
    uint32_t d;
    asm("cvt.rn.f16x2.f32 %0, %1, %2;" : "=r"(d) : "f"(hi), "f"(lo));
    return d;
}
__device__ __forceinline__ float ex2(float x) {
    float y;
    asm("ex2.approx.f32 %0, %1;" : "=f"(y) : "f"(x));
    return y;
}
__device__ __forceinline__ uint32_t sw128(uint32_t o) {
    return o ^ ((o >> 3) & 0x70);
}

#define CP_ASYNC16(dst, src) \
    asm volatile("cp.async.cg.shared.global [%0], [%1], 16;" :: "r"(dst), "l"(src))
#define CP_COMMIT() asm volatile("cp.async.commit_group;" ::: "memory")
#define CP_WAIT2() asm volatile("cp.async.wait_group 2;" ::: "memory")
#define CP_WAIT1() asm volatile("cp.async.wait_group 1;" ::: "memory")
#define CP_WAIT0() asm volatile("cp.async.wait_group 0;" ::: "memory")

extern __shared__ char dsm[];

// ---------------------------------------------------------------------------
// fp32 -> (fp16 hi, fp16 lo) split (x input)
// ---------------------------------------------------------------------------
__global__ __launch_bounds__(256) void split_f16(
    const float* __restrict__ in, __half* __restrict__ hi,
    __half* __restrict__ lo, int n)
{
    int i = (blockIdx.x * 256 + threadIdx.x) * 4;
    if (i >= n) return;
    float4 v = *(const float4*)(in + i);
    __half h0 = __float2half_rn(v.x), h1 = __float2half_rn(v.y);
    __half h2 = __float2half_rn(v.z), h3 = __float2half_rn(v.w);
    __half2 hp0 = __halves2half2(h0, h1), hp1 = __halves2half2(h2, h3);
    __half2 lp0 = __halves2half2(
        __float2half_rn(v.x - __half2float(h0)),
        __float2half_rn(v.y - __half2float(h1)));
    __half2 lp1 = __halves2half2(
        __float2half_rn(v.z - __half2float(h2)),
        __float2half_rn(v.w - __half2float(h3)));
    uint2 hv, lv;
    hv.x = *(uint32_t*)&hp0; hv.y = *(uint32_t*)&hp1;
    lv.x = *(uint32_t*)&lp0; lv.y = *(uint32_t*)&lp1;
    *(uint2*)(hi + i) = hv;
    *(uint2*)(lo + i) = lv;
}

// Fused 4-weight fp32 -> fp16 convert (hi only): blockIdx.y selects tensor
__global__ __launch_bounds__(256) void conv4_f16(
    const float* __restrict__ s0, const float* __restrict__ s1,
    const float* __restrict__ s2, const float* __restrict__ s3,
    __half* __restrict__ hi, int n)
{
    const int t = blockIdx.y;
    const float* s = (t == 0) ? s0 : (t == 1) ? s1 : (t == 2) ? s2 : s3;
    int i = (blockIdx.x * 256 + threadIdx.x) * 4;
    if (i >= n) return;
    float4 v = *(const float4*)(s + i);
    __half2 hp0 = __halves2half2(__float2half_rn(v.x), __float2half_rn(v.y));
    __half2 hp1 = __halves2half2(__float2half_rn(v.z), __float2half_rn(v.w));
    uint2 hv;
    hv.x = *(uint32_t*)&hp0; hv.y = *(uint32_t*)&hp1;
    *(uint2*)(hi + (size_t)t * n + i) = hv;
}

// ---------------------------------------------------------------------------
// fp16 2-term GEMM core: acc = (Ah + Al) . Wh^T   (R11-proven)
// 3-stage cp.async pipeline, K-chunk 32, 80B pitch.
// ---------------------------------------------------------------------------
#define PITCH2 80
#define ARR2 (128 * PITCH2)              // 10240
#define STAGE2 (3 * ARR2)                // 30720
#define NSTAGE 3
#define GEMM_SMEM (NSTAGE * STAGE2)      // 92160
#define NK2 (DD / 32)                    // 32 chunks

struct GemmAcc { float a[2][8][4]; };

__device__ __forceinline__ void gemm_mainloop(
    const __half* gA_h, const __half* gA_l, const __half* gW_h,
    int tid, int wm, int wn, GemmAcc& A)
{
    const uint32_t smem_base = smem_u32(dsm);
    const int lane = tid & 31;

    const int r0i = tid >> 2, q0i = tid & 3;
    const uint32_t sdst0 = (uint32_t)(r0i * PITCH2 + q0i * 16);
    const size_t gof0 = (size_t)r0i * DD + q0i * 8;
    const int r1i = (tid + 256) >> 2, q1i = tid & 3;
    const uint32_t sdst1 = (uint32_t)(r1i * PITCH2 + q1i * 16);
    const size_t gof1 = (size_t)r1i * DD + q1i * 8;

    const uint32_t offA = (uint32_t)((lane & 15) * PITCH2 + (lane >> 4) * 16);
    const int m8 = lane >> 3;
    const int radd = lane - ((m8 == 1 || m8 == 2) ? 8 : (m8 == 3 ? 16 : 0));
    const uint32_t offB = (uint32_t)(radd * PITCH2 + ((m8 & 1) ? 16 : 0));

    float (*acc)[8][4] = A.a;
    #pragma unroll
    for (int i = 0; i < 2; i++)
        #pragma unroll
        for (int j = 0; j < 8; j++)
            #pragma unroll
            for (int k = 0; k < 4; k++) acc[i][j][k] = 0.f;

    auto load_chunk = [&](int c) {
        uint32_t st = smem_base + (uint32_t)((c % NSTAGE) * STAGE2);
        size_t g0 = gof0 + (size_t)c * 32;
        size_t g1 = gof1 + (size_t)c * 32;
        CP_ASYNC16(st + 0*ARR2 + sdst0, (const char*)(gA_h + g0));
        CP_ASYNC16(st + 0*ARR2 + sdst1, (const char*)(gA_h + g1));
        CP_ASYNC16(st + 1*ARR2 + sdst0, (const char*)(gA_l + g0));
        CP_ASYNC16(st + 1*ARR2 + sdst1, (const char*)(gA_l + g1));
        CP_ASYNC16(st + 2*ARR2 + sdst0, (const char*)(gW_h + g0));
        CP_ASYNC16(st + 2*ARR2 + sdst1, (const char*)(gW_h + g1));
        CP_COMMIT();
    };

    load_chunk(0);
    load_chunk(1);

    for (int c = 0; c < NK2; c++) {
        if (c + 2 < NK2) {
            load_chunk(c + 2);
            CP_WAIT2();
        } else if (c + 1 < NK2) {
            CP_WAIT1();
        } else {
            CP_WAIT0();
        }
        __syncthreads();

        const uint32_t sb = smem_base + (uint32_t)((c % NSTAGE) * STAGE2);
        const uint32_t aBase = sb + (uint32_t)(wm * 32 * PITCH2) + offA;
        const uint32_t bBase = sb + 2*ARR2 + (uint32_t)(wn * 64 * PITCH2) + offB;

        #pragma unroll
        for (int ks = 0; ks < 2; ks++) {
            const uint32_t ko = (uint32_t)(ks * 32);
            uint32_t aH[2][4], aL[2][4], bb[4][4];
            ldsm4(aH[0], aBase + ko);
            ldsm4(aH[1], aBase + ko + 16 * PITCH2);
            ldsm4(aL[0], aBase + ko + ARR2);
            ldsm4(aL[1], aBase + ko + ARR2 + 16 * PITCH2);
            #pragma unroll
            for (int p = 0; p < 4; p++) ldsm4(bb[p], bBase + ko + p * 16 * PITCH2);

            #pragma unroll
            for (int mt = 0; mt < 2; mt++)
                #pragma unroll
                for (int nt = 0; nt < 8; nt++)
                    mma_f16(acc[mt][nt], aH[mt], &bb[nt >> 1][(nt & 1) * 2]);
            #pragma unroll
            for (int mt = 0; mt < 2; mt++)
                #pragma unroll
                for (int nt = 0; nt < 8; nt++)
                    mma_f16(acc[mt][nt], aL[mt], &bb[nt >> 1][(nt & 1) * 2]);
        }
        __syncthreads();
    }
}

// ---------------------------------------------------------------------------
// Merged QKV GEMM: writes fp16 outputs in head layout (B,H,S,HD).
// Q: hi+lo fp16 (pre-scaled by QSCALE); K: hi only; V: hi+lo.
// ---------------------------------------------------------------------------
__global__ __launch_bounds__(256)
void tc_gemm_qkv(const __half* __restrict__ Ah, const __half* __restrict__ Al,
                 const __half* __restrict__ Wh,
                 const float* __restrict__ bq, const float* __restrict__ bk,
                 const float* __restrict__ bv,
                 __half* __restrict__ Qh, __half* __restrict__ Ql,
                 __half* __restrict__ Kh,
                 __half* __restrict__ Vh, __half* __restrict__ Vl)
{
    const int tid = threadIdx.x;
    const int wid = tid >> 5, lane = tid & 31;
    const int wm = wid & 3, wn = wid >> 2;
    const int t = blockIdx.x >> 3;
    const int n0 = (blockIdx.x & 7) * 128;
    const int m0 = blockIdx.y * 128;

    const float* bias = (t == 0) ? bq : (t == 1) ? bk : bv;
    __half* outh = (t == 0) ? Qh : (t == 1) ? Kh : Vh;
    __half* outl = (t == 0) ? Ql : Vl;   // unused for t==1
    const float scale = (t == 0) ? QSCALE : 1.0f;

    GemmAcc A;
    gemm_mainloop(Ah + (size_t)m0 * DD, Al + (size_t)m0 * DD,
                  Wh + (size_t)t * NW + (size_t)n0 * DD,
                  tid, wm, wn, A);

    const int g = lane >> 2, tig = lane & 3;
    #pragma unroll
    for (int mt = 0; mt < 2; mt++) {
        #pragma unroll
        for (int nt = 0; nt < 8; nt++) {
            const int col = n0 + wn * 64 + nt * 8 + tig * 2;
            const float2 b2 = *(const float2*)&bias[col];
            const int r1 = m0 + wm * 32 + mt * 16 + g;
            const int r2 = r1 + 8;
            float v0 = (A.a[mt][nt][0] + b2.x) * scale;
            float v1 = (A.a[mt][nt][1] + b2.y) * scale;
            float v2 = (A.a[mt][nt][2] + b2.x) * scale;
            float v3 = (A.a[mt][nt][3] + b2.y) * scale;
            const int h = col >> 6, hd = col & 63;
            const int b1b = r1 >> 11, s1 = r1 & 2047;
            const int b2b = r2 >> 11, s2 = r2 & 2047;
            size_t i1 = (((size_t)(b1b * HH + h)) * SS + s1) * HD + hd;
            size_t i2 = (((size_t)(b2b * HH + h)) * SS + s2) * HD + hd;
            __half h0 = __float2half_rn(v0), h1 = __float2half_rn(v1);
            __half h2 = __float2half_rn(v2), h3 = __float2half_rn(v3);
            *(__half2*)&outh[i1] = __halves2half2(h0, h1);
            *(__half2*)&outh[i2] = __halves2half2(h2, h3);
            if (t != 1) {
                __half l0 = __float2half_rn(v0 - __half2float(h0));
                __half l1 = __float2half_rn(v1 - __half2float(h1));
                __half l2 = __float2half_rn(v2 - __half2float(h2));
                __half l3 = __float2half_rn(v3 - __half2float(h3));
                *(__half2*)&outl[i1] = __halves2half2(l0, l1);
                *(__half2*)&outl[i2] = __halves2half2(l2, l3);
            }
        }
    }
}

// ---------------------------------------------------------------------------
// Final projection GEMM: fp32 output (B,S,D)
// ---------------------------------------------------------------------------
__global__ __launch_bounds__(256)
void tc_gemm_out(const __half* __restrict__ Ah, const __half* __restrict__ Al,
                 const __half* __restrict__ Wh,
                 const float* __restrict__ bias, float* __restrict__ outf)
{
    const int tid = threadIdx.x;
    const int wid = tid >> 5, lane = tid & 31;
    const int wm = wid & 3, wn = wid >> 2;
    const int n0 = blockIdx.x * 128, m0 = blockIdx.y * 128;

    GemmAcc A;
    gemm_mainloop(Ah + (size_t)m0 * DD, Al + (size_t)m0 * DD,
                  Wh + (size_t)n0 * DD, tid, wm, wn, A);

    const int g = lane >> 2, tig = lane & 3;
    #pragma unroll
    for (int mt = 0; mt < 2; mt++) {
        #pragma unroll
        for (int nt = 0; nt < 8; nt++) {
            const int col = n0 + wn * 64 + nt * 8 + tig * 2;
            const float2 b2 = *(const float2*)&bias[col];
            const int r1 = m0 + wm * 32 + mt * 16 + g;
            const int r2 = r1 + 8;
            float2 w0, w1;
            w0.x = A.a[mt][nt][0] + b2.x; w0.y = A.a[mt][nt][1] + b2.y;
            w1.x = A.a[mt][nt][2] + b2.x; w1.y = A.a[mt][nt][3] + b2.y;
            *(float2*)&outf[(size_t)r1 * DD + col] = w0;
            *(float2*)&outf[(size_t)r2 * DD + col] = w1;
        }
    }
}

// ---------------------------------------------------------------------------
// Flash attention, fp16, SW128-packed smem, 3-stage KV ring, ONE barrier/tile.
//   S = (Qh + Ql) . Kh ; O += fp16(P) . (Vh + Vl)
// smem: Ql [0,16384) SW128 (128 rows x 128B); stages s=0..2 at 16384+s*24576:
//   Kh +0 (8192), Vh +8192, Vl +16384.  Qh staged transiently in stage 0+1.
// Key masks: ballot words in g_km global scratch (CTA slot x 3 stages x 2).
// ---------------------------------------------------------------------------
#define AQL_SZ 16384
#define AST_SZ 24576
#define AV_OFF 8192
#define ATT_SMEM (AQL_SZ + 3 * AST_SZ)   // 90112

__global__ __launch_bounds__(256, 2) void attn_mma(
    const __half* __restrict__ Qh, const __half* __restrict__ Ql,
    const __half* __restrict__ Kh,
    const __half* __restrict__ Vh, const __half* __restrict__ Vl,
    const int* __restrict__ am,
    __half* __restrict__ Oh, __half* __restrict__ Ol)
{
    const int tid = threadIdx.x, w = tid >> 5, lane = tid & 31;
    const int qt = (int)gridDim.x - 1 - (int)blockIdx.x;   // big tiles first
    const int h = blockIdx.y, b = blockIdx.z;
    const int q0 = qt * 128;
    const int ktmax = 2 * qt + 2;
    const int cta = (int)(blockIdx.x + gridDim.x * (blockIdx.y + gridDim.y * blockIdx.z));
    const size_t hoff = ((size_t)(b * HH + h)) * SS * HD;
    const __half *qhp = Qh + hoff, *qlp = Ql + hoff;
    const __half *khp = Kh + hoff;
    const __half *vhp = Vh + hoff, *vlp = Vl + hoff;

    const uint32_t sbase = smem_u32(dsm);

    // ---- Q staging: Ql persistent at 0, Qh transient at stage region ----
    #pragma unroll
    for (int i = 0; i < 4; i++) {
        int e = tid + i * 256; int r = e >> 3, c = e & 7;
        uint32_t d = sw128((uint32_t)(r * 128 + c * 16));
        const size_t g = (size_t)(q0 + r) * HD + c * 8;
        CP_ASYNC16(sbase + d, (const char*)(qlp + g));
        CP_ASYNC16(sbase + AQL_SZ + d, (const char*)(qhp + g));
    }
    CP_COMMIT();

    const int g = lane >> 2, tig2 = (lane & 3) * 2;
    const int row0 = w * 16 + g;
    const int grow0 = q0 + row0, grow1 = grow0 + 8;
    const bool qok0 = (am[b * SS + grow0] != 0);
    const bool qok1 = (am[b * SS + grow1] != 0);

    CP_WAIT0();
    __syncthreads();

    // fragment address bases (SW128 computed inline per ldsm)
    const uint32_t aRow = (uint32_t)((w * 16 + (lane & 15)) * 128 + (lane >> 4) * 16);
    const int m8 = lane >> 3;
    const int radd = lane - ((m8 == 1 || m8 == 2) ? 8 : (m8 == 3 ? 16 : 0));
    const uint32_t kRow = (uint32_t)(radd * 128 + ((m8 & 1) ? 16 : 0));
    const uint32_t vRow = (uint32_t)((((lane & 7) + ((lane >> 3) & 1) * 8)) * 128
                                     + (((lane >> 4) & 1) ? 16 : 0));

    uint32_t aQh[4][4];
    #pragma unroll
    for (int ks = 0; ks < 4; ks++)
        ldsm4(aQh[ks], sbase + AQL_SZ + sw128(aRow + ks * 32));

    const bool qall = __syncthreads_and(qok0 && qok1) != 0;  // frees Qh region too

    auto load_kv = [&](int kt) {
        const int t0 = kt * 64;
        uint32_t st = sbase + AQL_SZ + (uint32_t)((kt % 3) * AST_SZ);
        #pragma unroll
        for (int i = 0; i < 2; i++) {
            int e = tid + i * 256; int r = e >> 3, c = e & 7;
            size_t gg = (size_t)(t0 + r) * HD + c * 8;
            uint32_t d = sw128((uint32_t)(r * 128 + c * 16));
            CP_ASYNC16(st + d, (const char*)(khp + gg));
            CP_ASYNC16(st + AV_OFF + d, (const char*)(vhp + gg));
            CP_ASYNC16(st + 2*AV_OFF + d, (const char*)(vlp + gg));
        }
        if (tid < 64) {
            int v = am[b * SS + t0 + tid];
            unsigned bl = __ballot_sync(0xffffffffu, v != 0);
            if ((tid & 31) == 0)
                g_km[(cta * 3 + kt % 3) * 2 + (tid >> 5)] = bl;
        }
        CP_COMMIT();
    };
    load_kv(0);
    load_kv(1);

    float oacc[8][4];
    #pragma unroll
    for (int i = 0; i < 8; i++)
        #pragma unroll
        for (int j = 0; j < 4; j++) oacc[i][j] = 0.f;
    float m0 = NEGBIG, m1 = NEGBIG;
    float l0p = 0.f, l1p = 0.f;

    for (int kt = 0; kt < ktmax; kt++) {
        if (kt + 1 < ktmax) { CP_WAIT1(); } else { CP_WAIT0(); }
        __syncthreads();                 // the ONLY barrier per tile
        if (kt + 2 < ktmax) load_kv(kt + 2);

        const uint32_t sb = sbase + AQL_SZ + (uint32_t)((kt % 3) * AST_SZ);
        const int t0 = kt * 64;
        const uint32_t mlo = g_km[(cta * 3 + kt % 3) * 2 + 0];
        const uint32_t mhi = g_km[(cta * 3 + kt % 3) * 2 + 1];
        const bool fast = qall && ((mlo & mhi) == 0xffffffffu) && (t0 + 63 <= q0);

        // ---- S = (Qh + Ql) Kh ----
        float s[8][4];
        #pragma unroll
        for (int i = 0; i < 8; i++)
            #pragma unroll
            for (int j = 0; j < 4; j++) s[i][j] = 0.f;

        #pragma unroll
        for (int ks = 0; ks < 4; ks++) {
            uint32_t aQl_t[4];
            ldsm4(aQl_t, sbase + sw128(aRow + ks * 32));
            uint32_t kbh[4][4];
            #pragma unroll
            for (int p = 0; p < 4; p++)
                ldsm4(kbh[p], sb + sw128(kRow + (uint32_t)(p * 2048 + ks * 32)));
            #pragma unroll
            for (int nt = 0; nt < 8; nt++) {
                mma_f16(s[nt], aQh[ks], &kbh[nt >> 1][(nt & 1) * 2]);
                mma_f16(s[nt], aQl_t, &kbh[nt >> 1][(nt & 1) * 2]);
            }
        }

        // ---- mask (skipped on interior fully-valid tiles) ----
        if (!fast) {
            #pragma unroll
            for (int nt = 0; nt < 8; nt++) {
                const uint32_t word = (nt < 4) ? mlo : mhi;
                const int bit = (nt & 3) * 8 + tig2;
                int c0 = nt * 8 + tig2;
                int gc0 = t0 + c0, gc1 = gc0 + 1;
                bool k0 = ((word >> bit) & 1u) != 0;
                bool k1 = ((word >> (bit + 1)) & 1u) != 0;
                s[nt][0] = (qok0 && k0 && gc0 <= grow0) ? s[nt][0] : NEGBIG;
                s[nt][1] = (qok0 && k1 && gc1 <= grow0) ? s[nt][1] : NEGBIG;
                s[nt][2] = (qok1 && k0 && gc0 <= grow1) ? s[nt][2] : NEGBIG;
                s[nt][3] = (qok1 && k1 && gc1 <= grow1) ? s[nt][3] : NEGBIG;
            }
        }

        // ---- online softmax (base 2; max reduce only, sum deferred) ----
        float mx0 = NEGBIG, mx1 = NEGBIG;
        #pragma unroll
        for (int nt = 0; nt < 8; nt++) {
            mx0 = fmaxf(mx0, fmaxf(s[nt][0], s[nt][1]));
            mx1 = fmaxf(mx1, fmaxf(s[nt][2], s[nt][3]));
        }
        mx0 = fmaxf(mx0, __shfl_xor_sync(0xffffffffu, mx0, 1));
        mx0 = fmaxf(mx0, __shfl_xor_sync(0xffffffffu, mx0, 2));
        mx1 = fmaxf(mx1, __shfl_xor_sync(0xffffffffu, mx1, 1));
        mx1 = fmaxf(mx1, __shfl_xor_sync(0xffffffffu, mx1, 2));
        const float mn0 = fmaxf(m0, mx0), mn1 = fmaxf(m1, mx1);
        const float corr0 = ex2(m0 - mn0), corr1 = ex2(m1 - mn1);
        m0 = mn0; m1 = mn1;
        float sum0 = 0.f, sum1 = 0.f;
        #pragma unroll
        for (int nt = 0; nt < 8; nt++) {
            s[nt][0] = ex2(s[nt][0] - mn0);
            s[nt][1] = ex2(s[nt][1] - mn0);
            s[nt][2] = ex2(s[nt][2] - mn1);
            s[nt][3] = ex2(s[nt][3] - mn1);
            sum0 += s[nt][0] + s[nt][1];
            sum1 += s[nt][2] + s[nt][3];
        }
        l0p = l0p * corr0 + sum0;
        l1p = l1p * corr1 + sum1;
        #pragma unroll
        for (int dt = 0; dt < 8; dt++) {
            oacc[dt][0] *= corr0; oacc[dt][1] *= corr0;
            oacc[dt][2] *= corr1; oacc[dt][3] *= corr1;
        }

        // ---- O += fp16(P) (Vh + Vl) ----
        #pragma unroll
        for (int ts = 0; ts < 4; ts++) {
            uint32_t aP[4];
            aP[0] = pack_f16(s[2*ts][0], s[2*ts][1]);
            aP[1] = pack_f16(s[2*ts][2], s[2*ts][3]);
            aP[2] = pack_f16(s[2*ts+1][0], s[2*ts+1][1]);
            aP[3] = pack_f16(s[2*ts+1][2], s[2*ts+1][3]);

            uint32_t vbh[4][4], vbl[4][4];
            #pragma unroll
            for (int dp = 0; dp < 4; dp++) {
                uint32_t o = sw128(vRow + (uint32_t)(ts * 2048 + dp * 32));
                ldsm4t(vbh[dp], sb + AV_OFF + o);
                ldsm4t(vbl[dp], sb + 2*AV_OFF + o);
            }
            #pragma unroll
            for (int dt = 0; dt < 8; dt++) {
                mma_f16(oacc[dt], aP, &vbh[dt >> 1][(dt & 1) * 2]);
                mma_f16(oacc[dt], aP, &vbl[dt >> 1][(dt & 1) * 2]);
            }
        }
        // no trailing barrier: 3-stage ring; overwrite target is 2 tiles ahead
    }

    // ---- epilogue: reduce l partials once, normalize, hi/lo fp16 ----
    float l0 = l0p, l1 = l1p;
    l0 += __shfl_xor_sync(0xffffffffu, l0, 1);
    l0 += __shfl_xor_sync(0xffffffffu, l0, 2);
    l1 += __shfl_xor_sync(0xffffffffu, l1, 1);
    l1 += __shfl_xor_sync(0xffffffffu, l1, 2);
    const float inv0 = (l0 > 0.f) ? (1.f / l0) : 0.f;
    const float inv1 = (l1 > 0.f) ? (1.f / l1) : 0.f;
    const size_t o0 = ((size_t)(b * SS + grow0)) * DD + h * HD;
    const size_t o1 = ((size_t)(b * SS + grow1)) * DD + h * HD;
    #pragma unroll
    for (int dt = 0; dt < 8; dt++) {
        int dc = dt * 8 + tig2;
        float v0 = oacc[dt][0] * inv0, v1 = oacc[dt][1] * inv0;
        float v2 = oacc[dt][2] * inv1, v3 = oacc[dt][3] * inv1;
        __half h0 = __float2half_rn(v0), h1 = __float2half_rn(v1);
        __half h2 = __float2half_rn(v2), h3 = __float2half_rn(v3);
        *(__half2*)&Oh[o0 + dc] = __halves2half2(h0, h1);
        *(__half2*)&Oh[o1 + dc] = __halves2half2(h2, h3);
        *(__half2*)&Ol[o0 + dc] = __halves2half2(
            __float2half_rn(v0 - __half2float(h0)),
            __float2half_rn(v1 - __half2float(h1)));
        *(__half2*)&Ol[o1 + dc] = __halves2half2(
            __float2half_rn(v2 - __half2float(h2)),
            __float2half_rn(v3 - __half2float(h3)));
    }
}

// ---------------------------------------------------------------------------
extern "C" void kernel_launch(void* const* d_in, const int* in_sizes, int n_in,
                              void* d_out, int out_size)
{
    (void)in_sizes; (void)n_in; (void)out_size;
    const float* x  = (const float*)d_in[0];
    const int*   am = (const int*)d_in[1];
    const float* Wq = (const float*)d_in[2];
    const float* bq = (const float*)d_in[3];
    const float* Wk = (const float*)d_in[4];
    const float* bk = (const float*)d_in[5];
    const float* Wv = (const float*)d_in[6];
    const float* bv = (const float*)d_in[7];
    const float* Wp = (const float*)d_in[8];
    const float* bp = (const float*)d_in[9];
    float* out = (float*)d_out;

    __half *xh, *xl, *wh, *ah, *al;
    __half *qh, *ql, *kh, *vh, *vl;
    cudaGetSymbolAddress((void**)&xh, gx_h);
    cudaGetSymbolAddress((void**)&xl, gx_l);
    cudaGetSymbolAddress((void**)&wh, gw_h);
    cudaGetSymbolAddress((void**)&ah, ga_h);
    cudaGetSymbolAddress((void**)&al, ga_l);
    cudaGetSymbolAddress((void**)&qh, gQh);
    cudaGetSymbolAddress((void**)&ql, gQl);
    cudaGetSymbolAddress((void**)&kh, gKh);
    cudaGetSymbolAddress((void**)&vh, gVh);
    cudaGetSymbolAddress((void**)&vl, gVl);

    cudaFuncSetAttribute(tc_gemm_qkv,
                         cudaFuncAttributeMaxDynamicSharedMemorySize, GEMM_SMEM);
    cudaFuncSetAttribute(tc_gemm_out,
                         cudaFuncAttributeMaxDynamicSharedMemorySize, GEMM_SMEM);
    cudaFuncSetAttribute(attn_mma,
                         cudaFuncAttributeMaxDynamicSharedMemorySize, ATT_SMEM);

    const int NX = MM * DD;

    split_f16<<<NX/1024, 256>>>(x, xh, xl, NX);
    conv4_f16<<<dim3(NW/1024, 4), 256>>>(Wq, Wk, Wv, Wp, wh, NW);

    tc_gemm_qkv<<<dim3(24, MM/128), 256, GEMM_SMEM>>>(
        xh, xl, wh, bq, bk, bv, qh, ql, kh, vh, vl);

    attn_mma<<<dim3(SS/128, HH, BB), 256, ATT_SMEM>>>(qh, ql, kh, vh, vl,
                                                      am, ah, al);

    tc_gemm_out<<<dim3(DD/128, MM/128), 256, GEMM_SMEM>>>(
        ah, al, wh + 3*NW, bp, out);
}

// round 17
// speedup vs baseline: 1.3639x; 1.0034x over previous
#include <cuda_runtime.h>
#include <cuda_bf16.h>
#include <cuda_fp16.h>
#include <cstdint>
#include <math.h>

// Problem constants
#define BB 2
#define SS 2048
#define DD 1024
#define HH 16
#define HD 64
#define MM (BB*SS)
#define NW (DD*DD)

#define NEGBIG (-1e30f)
// 0.125 * log2(e): folds attention scale and base-2 softmax into Q
#define QSCALE 0.1803368801111204f

// ---------------------------------------------------------------------------
// Scratch (no cudaMalloc allowed) — all fp16
// ---------------------------------------------------------------------------
__device__ __half gx_h[MM*DD];
__device__ __half gx_l[MM*DD];
__device__ __half gw_h[4*DD*DD];       // weights: fp16 hi only
__device__ __half gQh[MM*DD];          // (B,H,S,HD) fp16 hi/lo
__device__ __half gQl[MM*DD];
__device__ __half gKh[MM*DD];          // K: fp16 hi only
__device__ __half gVh[MM*DD];
__device__ __half gVl[MM*DD];
__device__ __half ga_h[MM*DD];         // attention out (B,S,D) fp16 hi/lo
__device__ __half ga_l[MM*DD];
__device__ uint32_t g_km[512 * 3 * 2]; // per-CTA key-mask ballot words

// ---------------------------------------------------------------------------
// PTX helpers (plain sm_103-safe: mma.sync / ldmatrix / cp.async)
// ---------------------------------------------------------------------------
__device__ __forceinline__ uint32_t smem_u32(const void* p) {
    uint32_t a;
    asm("{ .reg .u64 t; cvta.to.shared.u64 t, %1; cvt.u32.u64 %0, t; }" : "=r"(a) : "l"(p));
    return a;
}

__device__ __forceinline__ void mma_f16(float* c, const uint32_t* a, const uint32_t* b) {
    asm volatile(
        "mma.sync.aligned.m16n8k16.row.col.f32.f16.f16.f32 "
        "{%0,%1,%2,%3}, {%4,%5,%6,%7}, {%8,%9}, {%0,%1,%2,%3};"
        : "+f"(c[0]), "+f"(c[1]), "+f"(c[2]), "+f"(c[3])
        : "r"(a[0]), "r"(a[1]), "r"(a[2]), "r"(a[3]), "r"(b[0]), "r"(b[1]));
}

__device__ __forceinline__ void ldsm4(uint32_t* r, uint32_t addr) {
    asm volatile("ldmatrix.sync.aligned.m8n8.x4.shared.b16 {%0,%1,%2,%3}, [%4];"
        : "=r"(r[0]), "=r"(r[1]), "=r"(r[2]), "=r"(r[3]) : "r"(addr));
}
__device__ __forceinline__ void ldsm4t(uint32_t* r, uint32_t addr) {
    asm volatile("ldmatrix.sync.aligned.m8n8.x4.trans.shared.b16 {%0,%1,%2,%3}, [%4];"
        : "=r"(r[0]), "=r"(r[1]), "=r"(r[2]), "=r"(r[3]) : "r"(addr));
}
__device__ __forceinline__ uint32_t pack_f16(float lo, float hi) {
    uint32_t d;
    asm("cvt.rn.f16x2.f32 %0, %1, %2;" : "=r"(d) : "f"(hi), "f"(lo));
    return d;
}
__device__ __forceinline__ float ex2(float x) {
    float y;
    asm("ex2.approx.f32 %0, %1;" : "=f"(y) : "f"(x));
    return y;
}
__device__ __forceinline__ uint32_t sw128(uint32_t o) {
    return o ^ ((o >> 3) & 0x70);
}

#define CP_ASYNC16(dst, src) \
    asm volatile("cp.async.cg.shared.global [%0], [%1], 16;" :: "r"(dst), "l"(src))
#define CP_COMMIT() asm volatile("cp.async.commit_group;" ::: "memory")
#define CP_WAIT2() asm volatile("cp.async.wait_group 2;" ::: "memory")
#define CP_WAIT1() asm volatile("cp.async.wait_group 1;" ::: "memory")
#define CP_WAIT0() asm volatile("cp.async.wait_group 0;" ::: "memory")

extern __shared__ char dsm[];

// ---------------------------------------------------------------------------
// fp32 -> (fp16 hi, fp16 lo) split (x input)
// ---------------------------------------------------------------------------
__global__ __launch_bounds__(256) void split_f16(
    const float* __restrict__ in, __half* __restrict__ hi,
    __half* __restrict__ lo, int n)
{
    int i = (blockIdx.x * 256 + threadIdx.x) * 4;
    if (i >= n) return;
    float4 v = *(const float4*)(in + i);
    __half h0 = __float2half_rn(v.x), h1 = __float2half_rn(v.y);
    __half h2 = __float2half_rn(v.z), h3 = __float2half_rn(v.w);
    __half2 hp0 = __halves2half2(h0, h1), hp1 = __halves2half2(h2, h3);
    __half2 lp0 = __halves2half2(
        __float2half_rn(v.x - __half2float(h0)),
        __float2half_rn(v.y - __half2float(h1)));
    __half2 lp1 = __halves2half2(
        __float2half_rn(v.z - __half2float(h2)),
        __float2half_rn(v.w - __half2float(h3)));
    uint2 hv, lv;
    hv.x = *(uint32_t*)&hp0; hv.y = *(uint32_t*)&hp1;
    lv.x = *(uint32_t*)&lp0; lv.y = *(uint32_t*)&lp1;
    *(uint2*)(hi + i) = hv;
    *(uint2*)(lo + i) = lv;
}

// Fused 4-weight fp32 -> fp16 convert (hi only): blockIdx.y selects tensor
__global__ __launch_bounds__(256) void conv4_f16(
    const float* __restrict__ s0, const float* __restrict__ s1,
    const float* __restrict__ s2, const float* __restrict__ s3,
    __half* __restrict__ hi, int n)
{
    const int t = blockIdx.y;
    const float* s = (t == 0) ? s0 : (t == 1) ? s1 : (t == 2) ? s2 : s3;
    int i = (blockIdx.x * 256 + threadIdx.x) * 4;
    if (i >= n) return;
    float4 v = *(const float4*)(s + i);
    __half2 hp0 = __halves2half2(__float2half_rn(v.x), __float2half_rn(v.y));
    __half2 hp1 = __halves2half2(__float2half_rn(v.z), __float2half_rn(v.w));
    uint2 hv;
    hv.x = *(uint32_t*)&hp0; hv.y = *(uint32_t*)&hp1;
    *(uint2*)(hi + (size_t)t * n + i) = hv;
}

// ---------------------------------------------------------------------------
// fp16 2-term GEMM core: acc = (Ah + Al) . Wh^T
// 3-stage cp.async ring, K-chunk 32, 80B pitch.
// R17: ONE barrier per chunk; prefetch issued right after the barrier
// (same proven pattern as the R16 attention ring).
// ---------------------------------------------------------------------------
#define PITCH2 80
#define ARR2 (128 * PITCH2)              // 10240
#define STAGE2 (3 * ARR2)                // 30720
#define NSTAGE 3
#define GEMM_SMEM (NSTAGE * STAGE2)      // 92160
#define NK2 (DD / 32)                    // 32 chunks

struct GemmAcc { float a[2][8][4]; };

__device__ __forceinline__ void gemm_mainloop(
    const __half* gA_h, const __half* gA_l, const __half* gW_h,
    int tid, int wm, int wn, GemmAcc& A)
{
    const uint32_t smem_base = smem_u32(dsm);
    const int lane = tid & 31;

    const int r0i = tid >> 2, q0i = tid & 3;
    const uint32_t sdst0 = (uint32_t)(r0i * PITCH2 + q0i * 16);
    const size_t gof0 = (size_t)r0i * DD + q0i * 8;
    const int r1i = (tid + 256) >> 2, q1i = tid & 3;
    const uint32_t sdst1 = (uint32_t)(r1i * PITCH2 + q1i * 16);
    const size_t gof1 = (size_t)r1i * DD + q1i * 8;

    const uint32_t offA = (uint32_t)((lane & 15) * PITCH2 + (lane >> 4) * 16);
    const int m8 = lane >> 3;
    const int radd = lane - ((m8 == 1 || m8 == 2) ? 8 : (m8 == 3 ? 16 : 0));
    const uint32_t offB = (uint32_t)(radd * PITCH2 + ((m8 & 1) ? 16 : 0));

    float (*acc)[8][4] = A.a;
    #pragma unroll
    for (int i = 0; i < 2; i++)
        #pragma unroll
        for (int j = 0; j < 8; j++)
            #pragma unroll
            for (int k = 0; k < 4; k++) acc[i][j][k] = 0.f;

    auto load_chunk = [&](int c) {
        uint32_t st = smem_base + (uint32_t)((c % NSTAGE) * STAGE2);
        size_t g0 = gof0 + (size_t)c * 32;
        size_t g1 = gof1 + (size_t)c * 32;
        CP_ASYNC16(st + 0*ARR2 + sdst0, (const char*)(gA_h + g0));
        CP_ASYNC16(st + 0*ARR2 + sdst1, (const char*)(gA_h + g1));
        CP_ASYNC16(st + 1*ARR2 + sdst0, (const char*)(gA_l + g0));
        CP_ASYNC16(st + 1*ARR2 + sdst1, (const char*)(gA_l + g1));
        CP_ASYNC16(st + 2*ARR2 + sdst0, (const char*)(gW_h + g0));
        CP_ASYNC16(st + 2*ARR2 + sdst1, (const char*)(gW_h + g1));
        CP_COMMIT();
    };

    load_chunk(0);
    load_chunk(1);

    for (int c = 0; c < NK2; c++) {
        if (c + 1 < NK2) { CP_WAIT1(); } else { CP_WAIT0(); }
        __syncthreads();                 // the ONLY barrier per chunk
        if (c + 2 < NK2) load_chunk(c + 2);   // stage (c+2)%3 == (c-1)%3, free

        const uint32_t sb = smem_base + (uint32_t)((c % NSTAGE) * STAGE2);
        const uint32_t aBase = sb + (uint32_t)(wm * 32 * PITCH2) + offA;
        const uint32_t bBase = sb + 2*ARR2 + (uint32_t)(wn * 64 * PITCH2) + offB;

        #pragma unroll
        for (int ks = 0; ks < 2; ks++) {
            const uint32_t ko = (uint32_t)(ks * 32);
            uint32_t aH[2][4], aL[2][4], bb[4][4];
            ldsm4(aH[0], aBase + ko);
            ldsm4(aH[1], aBase + ko + 16 * PITCH2);
            ldsm4(aL[0], aBase + ko + ARR2);
            ldsm4(aL[1], aBase + ko + ARR2 + 16 * PITCH2);
            #pragma unroll
            for (int p = 0; p < 4; p++) ldsm4(bb[p], bBase + ko + p * 16 * PITCH2);

            #pragma unroll
            for (int mt = 0; mt < 2; mt++)
                #pragma unroll
                for (int nt = 0; nt < 8; nt++)
                    mma_f16(acc[mt][nt], aH[mt], &bb[nt >> 1][(nt & 1) * 2]);
            #pragma unroll
            for (int mt = 0; mt < 2; mt++)
                #pragma unroll
                for (int nt = 0; nt < 8; nt++)
                    mma_f16(acc[mt][nt], aL[mt], &bb[nt >> 1][(nt & 1) * 2]);
        }
        // no trailing barrier: 3-stage ring, overwrite target is 2 chunks ahead
    }
}

// ---------------------------------------------------------------------------
// Merged QKV GEMM: writes fp16 outputs in head layout (B,H,S,HD).
// Q: hi+lo fp16 (pre-scaled by QSCALE); K: hi only; V: hi+lo.
// ---------------------------------------------------------------------------
__global__ __launch_bounds__(256)
void tc_gemm_qkv(const __half* __restrict__ Ah, const __half* __restrict__ Al,
                 const __half* __restrict__ Wh,
                 const float* __restrict__ bq, const float* __restrict__ bk,
                 const float* __restrict__ bv,
                 __half* __restrict__ Qh, __half* __restrict__ Ql,
                 __half* __restrict__ Kh,
                 __half* __restrict__ Vh, __half* __restrict__ Vl)
{
    const int tid = threadIdx.x;
    const int wid = tid >> 5, lane = tid & 31;
    const int wm = wid & 3, wn = wid >> 2;
    const int t = blockIdx.x >> 3;
    const int n0 = (blockIdx.x & 7) * 128;
    const int m0 = blockIdx.y * 128;

    const float* bias = (t == 0) ? bq : (t == 1) ? bk : bv;
    __half* outh = (t == 0) ? Qh : (t == 1) ? Kh : Vh;
    __half* outl = (t == 0) ? Ql : Vl;   // unused for t==1
    const float scale = (t == 0) ? QSCALE : 1.0f;

    GemmAcc A;
    gemm_mainloop(Ah + (size_t)m0 * DD, Al + (size_t)m0 * DD,
                  Wh + (size_t)t * NW + (size_t)n0 * DD,
                  tid, wm, wn, A);

    const int g = lane >> 2, tig = lane & 3;
    #pragma unroll
    for (int mt = 0; mt < 2; mt++) {
        #pragma unroll
        for (int nt = 0; nt < 8; nt++) {
            const int col = n0 + wn * 64 + nt * 8 + tig * 2;
            const float2 b2 = *(const float2*)&bias[col];
            const int r1 = m0 + wm * 32 + mt * 16 + g;
            const int r2 = r1 + 8;
            float v0 = (A.a[mt][nt][0] + b2.x) * scale;
            float v1 = (A.a[mt][nt][1] + b2.y) * scale;
            float v2 = (A.a[mt][nt][2] + b2.x) * scale;
            float v3 = (A.a[mt][nt][3] + b2.y) * scale;
            const int h = col >> 6, hd = col & 63;
            const int b1b = r1 >> 11, s1 = r1 & 2047;
            const int b2b = r2 >> 11, s2 = r2 & 2047;
            size_t i1 = (((size_t)(b1b * HH + h)) * SS + s1) * HD + hd;
            size_t i2 = (((size_t)(b2b * HH + h)) * SS + s2) * HD + hd;
            __half h0 = __float2half_rn(v0), h1 = __float2half_rn(v1);
            __half h2 = __float2half_rn(v2), h3 = __float2half_rn(v3);
            *(__half2*)&outh[i1] = __halves2half2(h0, h1);
            *(__half2*)&outh[i2] = __halves2half2(h2, h3);
            if (t != 1) {
                __half l0 = __float2half_rn(v0 - __half2float(h0));
                __half l1 = __float2half_rn(v1 - __half2float(h1));
                __half l2 = __float2half_rn(v2 - __half2float(h2));
                __half l3 = __float2half_rn(v3 - __half2float(h3));
                *(__half2*)&outl[i1] = __halves2half2(l0, l1);
                *(__half2*)&outl[i2] = __halves2half2(l2, l3);
            }
        }
    }
}

// ---------------------------------------------------------------------------
// Final projection GEMM: fp32 output (B,S,D)
// ---------------------------------------------------------------------------
__global__ __launch_bounds__(256)
void tc_gemm_out(const __half* __restrict__ Ah, const __half* __restrict__ Al,
                 const __half* __restrict__ Wh,
                 const float* __restrict__ bias, float* __restrict__ outf)
{
    const int tid = threadIdx.x;
    const int wid = tid >> 5, lane = tid & 31;
    const int wm = wid & 3, wn = wid >> 2;
    const int n0 = blockIdx.x * 128, m0 = blockIdx.y * 128;

    GemmAcc A;
    gemm_mainloop(Ah + (size_t)m0 * DD, Al + (size_t)m0 * DD,
                  Wh + (size_t)n0 * DD, tid, wm, wn, A);

    const int g = lane >> 2, tig = lane & 3;
    #pragma unroll
    for (int mt = 0; mt < 2; mt++) {
        #pragma unroll
        for (int nt = 0; nt < 8; nt++) {
            const int col = n0 + wn * 64 + nt * 8 + tig * 2;
            const float2 b2 = *(const float2*)&bias[col];
            const int r1 = m0 + wm * 32 + mt * 16 + g;
            const int r2 = r1 + 8;
            float2 w0, w1;
            w0.x = A.a[mt][nt][0] + b2.x; w0.y = A.a[mt][nt][1] + b2.y;
            w1.x = A.a[mt][nt][2] + b2.x; w1.y = A.a[mt][nt][3] + b2.y;
            *(float2*)&outf[(size_t)r1 * DD + col] = w0;
            *(float2*)&outf[(size_t)r2 * DD + col] = w1;
        }
    }
}

// ---------------------------------------------------------------------------
// Flash attention (R16-proven): fp16, SW128 smem, 3-stage KV ring,
// ONE barrier per tile.  S = (Qh + Ql) . Kh ; O += fp16(P) . (Vh + Vl)
// ---------------------------------------------------------------------------
#define AQL_SZ 16384
#define AST_SZ 24576
#define AV_OFF 8192
#define ATT_SMEM (AQL_SZ + 3 * AST_SZ)   // 90112

__global__ __launch_bounds__(256, 2) void attn_mma(
    const __half* __restrict__ Qh, const __half* __restrict__ Ql,
    const __half* __restrict__ Kh,
    const __half* __restrict__ Vh, const __half* __restrict__ Vl,
    const int* __restrict__ am,
    __half* __restrict__ Oh, __half* __restrict__ Ol)
{
    const int tid = threadIdx.x, w = tid >> 5, lane = tid & 31;
    const int qt = (int)gridDim.x - 1 - (int)blockIdx.x;   // big tiles first
    const int h = blockIdx.y, b = blockIdx.z;
    const int q0 = qt * 128;
    const int ktmax = 2 * qt + 2;
    const int cta = (int)(blockIdx.x + gridDim.x * (blockIdx.y + gridDim.y * blockIdx.z));
    const size_t hoff = ((size_t)(b * HH + h)) * SS * HD;
    const __half *qhp = Qh + hoff, *qlp = Ql + hoff;
    const __half *khp = Kh + hoff;
    const __half *vhp = Vh + hoff, *vlp = Vl + hoff;

    const uint32_t sbase = smem_u32(dsm);

    // ---- Q staging: Ql persistent at 0, Qh transient at stage region ----
    #pragma unroll
    for (int i = 0; i < 4; i++) {
        int e = tid + i * 256; int r = e >> 3, c = e & 7;
        uint32_t d = sw128((uint32_t)(r * 128 + c * 16));
        const size_t g = (size_t)(q0 + r) * HD + c * 8;
        CP_ASYNC16(sbase + d, (const char*)(qlp + g));
        CP_ASYNC16(sbase + AQL_SZ + d, (const char*)(qhp + g));
    }
    CP_COMMIT();

    const int g = lane >> 2, tig2 = (lane & 3) * 2;
    const int row0 = w * 16 + g;
    const int grow0 = q0 + row0, grow1 = grow0 + 8;
    const bool qok0 = (am[b * SS + grow0] != 0);
    const bool qok1 = (am[b * SS + grow1] != 0);

    CP_WAIT0();
    __syncthreads();

    const uint32_t aRow = (uint32_t)((w * 16 + (lane & 15)) * 128 + (lane >> 4) * 16);
    const int m8 = lane >> 3;
    const int radd = lane - ((m8 == 1 || m8 == 2) ? 8 : (m8 == 3 ? 16 : 0));
    const uint32_t kRow = (uint32_t)(radd * 128 + ((m8 & 1) ? 16 : 0));
    const uint32_t vRow = (uint32_t)((((lane & 7) + ((lane >> 3) & 1) * 8)) * 128
                                     + (((lane >> 4) & 1) ? 16 : 0));

    uint32_t aQh[4][4];
    #pragma unroll
    for (int ks = 0; ks < 4; ks++)
        ldsm4(aQh[ks], sbase + AQL_SZ + sw128(aRow + ks * 32));

    const bool qall = __syncthreads_and(qok0 && qok1) != 0;  // frees Qh region too

    auto load_kv = [&](int kt) {
        const int t0 = kt * 64;
        uint32_t st = sbase + AQL_SZ + (uint32_t)((kt % 3) * AST_SZ);
        #pragma unroll
        for (int i = 0; i < 2; i++) {
            int e = tid + i * 256; int r = e >> 3, c = e & 7;
            size_t gg = (size_t)(t0 + r) * HD + c * 8;
            uint32_t d = sw128((uint32_t)(r * 128 + c * 16));
            CP_ASYNC16(st + d, (const char*)(khp + gg));
            CP_ASYNC16(st + AV_OFF + d, (const char*)(vhp + gg));
            CP_ASYNC16(st + 2*AV_OFF + d, (const char*)(vlp + gg));
        }
        if (tid < 64) {
            int v = am[b * SS + t0 + tid];
            unsigned bl = __ballot_sync(0xffffffffu, v != 0);
            if ((tid & 31) == 0)
                g_km[(cta * 3 + kt % 3) * 2 + (tid >> 5)] = bl;
        }
        CP_COMMIT();
    };
    load_kv(0);
    load_kv(1);

    float oacc[8][4];
    #pragma unroll
    for (int i = 0; i < 8; i++)
        #pragma unroll
        for (int j = 0; j < 4; j++) oacc[i][j] = 0.f;
    float m0 = NEGBIG, m1 = NEGBIG;
    float l0p = 0.f, l1p = 0.f;

    for (int kt = 0; kt < ktmax; kt++) {
        if (kt + 1 < ktmax) { CP_WAIT1(); } else { CP_WAIT0(); }
        __syncthreads();                 // the ONLY barrier per tile
        if (kt + 2 < ktmax) load_kv(kt + 2);

        const uint32_t sb = sbase + AQL_SZ + (uint32_t)((kt % 3) * AST_SZ);
        const int t0 = kt * 64;
        const uint32_t mlo = g_km[(cta * 3 + kt % 3) * 2 + 0];
        const uint32_t mhi = g_km[(cta * 3 + kt % 3) * 2 + 1];
        const bool fast = qall && ((mlo & mhi) == 0xffffffffu) && (t0 + 63 <= q0);

        // ---- S = (Qh + Ql) Kh ----
        float s[8][4];
        #pragma unroll
        for (int i = 0; i < 8; i++)
            #pragma unroll
            for (int j = 0; j < 4; j++) s[i][j] = 0.f;

        #pragma unroll
        for (int ks = 0; ks < 4; ks++) {
            uint32_t aQl_t[4];
            ldsm4(aQl_t, sbase + sw128(aRow + ks * 32));
            uint32_t kbh[4][4];
            #pragma unroll
            for (int p = 0; p < 4; p++)
                ldsm4(kbh[p], sb + sw128(kRow + (uint32_t)(p * 2048 + ks * 32)));
            #pragma unroll
            for (int nt = 0; nt < 8; nt++) {
                mma_f16(s[nt], aQh[ks], &kbh[nt >> 1][(nt & 1) * 2]);
                mma_f16(s[nt], aQl_t, &kbh[nt >> 1][(nt & 1) * 2]);
            }
        }

        // ---- mask (skipped on interior fully-valid tiles) ----
        if (!fast) {
            #pragma unroll
            for (int nt = 0; nt < 8; nt++) {
                const uint32_t word = (nt < 4) ? mlo : mhi;
                const int bit = (nt & 3) * 8 + tig2;
                int c0 = nt * 8 + tig2;
                int gc0 = t0 + c0, gc1 = gc0 + 1;
                bool k0 = ((word >> bit) & 1u) != 0;
                bool k1 = ((word >> (bit + 1)) & 1u) != 0;
                s[nt][0] = (qok0 && k0 && gc0 <= grow0) ? s[nt][0] : NEGBIG;
                s[nt][1] = (qok0 && k1 && gc1 <= grow0) ? s[nt][1] : NEGBIG;
                s[nt][2] = (qok1 && k0 && gc0 <= grow1) ? s[nt][2] : NEGBIG;
                s[nt][3] = (qok1 && k1 && gc1 <= grow1) ? s[nt][3] : NEGBIG;
            }
        }

        // ---- online softmax (base 2; max reduce only, sum deferred) ----
        float mx0 = NEGBIG, mx1 = NEGBIG;
        #pragma unroll
        for (int nt = 0; nt < 8; nt++) {
            mx0 = fmaxf(mx0, fmaxf(s[nt][0], s[nt][1]));
            mx1 = fmaxf(mx1, fmaxf(s[nt][2], s[nt][3]));
        }
        mx0 = fmaxf(mx0, __shfl_xor_sync(0xffffffffu, mx0, 1));
        mx0 = fmaxf(mx0, __shfl_xor_sync(0xffffffffu, mx0, 2));
        mx1 = fmaxf(mx1, __shfl_xor_sync(0xffffffffu, mx1, 1));
        mx1 = fmaxf(mx1, __shfl_xor_sync(0xffffffffu, mx1, 2));
        const float mn0 = fmaxf(m0, mx0), mn1 = fmaxf(m1, mx1);
        const float corr0 = ex2(m0 - mn0), corr1 = ex2(m1 - mn1);
        m0 = mn0; m1 = mn1;
        float sum0 = 0.f, sum1 = 0.f;
        #pragma unroll
        for (int nt = 0; nt < 8; nt++) {
            s[nt][0] = ex2(s[nt][0] - mn0);
            s[nt][1] = ex2(s[nt][1] - mn0);
            s[nt][2] = ex2(s[nt][2] - mn1);
            s[nt][3] = ex2(s[nt][3] - mn1);
            sum0 += s[nt][0] + s[nt][1];
            sum1 += s[nt][2] + s[nt][3];
        }
        l0p = l0p * corr0 + sum0;
        l1p = l1p * corr1 + sum1;
        #pragma unroll
        for (int dt = 0; dt < 8; dt++) {
            oacc[dt][0] *= corr0; oacc[dt][1] *= corr0;
            oacc[dt][2] *= corr1; oacc[dt][3] *= corr1;
        }

        // ---- O += fp16(P) (Vh + Vl) ----
        #pragma unroll
        for (int ts = 0; ts < 4; ts++) {
            uint32_t aP[4];
            aP[0] = pack_f16(s[2*ts][0], s[2*ts][1]);
            aP[1] = pack_f16(s[2*ts][2], s[2*ts][3]);
            aP[2] = pack_f16(s[2*ts+1][0], s[2*ts+1][1]);
            aP[3] = pack_f16(s[2*ts+1][2], s[2*ts+1][3]);

            uint32_t vbh[4][4], vbl[4][4];
            #pragma unroll
            for (int dp = 0; dp < 4; dp++) {
                uint32_t o = sw128(vRow + (uint32_t)(ts * 2048 + dp * 32));
                ldsm4t(vbh[dp], sb + AV_OFF + o);
                ldsm4t(vbl[dp], sb + 2*AV_OFF + o);
            }
            #pragma unroll
            for (int dt = 0; dt < 8; dt++) {
                mma_f16(oacc[dt], aP, &vbh[dt >> 1][(dt & 1) * 2]);
                mma_f16(oacc[dt], aP, &vbl[dt >> 1][(dt & 1) * 2]);
            }
        }
        // no trailing barrier: 3-stage ring
    }

    // ---- epilogue: reduce l partials once, normalize, hi/lo fp16 ----
    float l0 = l0p, l1 = l1p;
    l0 += __shfl_xor_sync(0xffffffffu, l0, 1);
    l0 += __shfl_xor_sync(0xffffffffu, l0, 2);
    l1 += __shfl_xor_sync(0xffffffffu, l1, 1);
    l1 += __shfl_xor_sync(0xffffffffu, l1, 2);
    const float inv0 = (l0 > 0.f) ? (1.f / l0) : 0.f;
    const float inv1 = (l1 > 0.f) ? (1.f / l1) : 0.f;
    const size_t o0 = ((size_t)(b * SS + grow0)) * DD + h * HD;
    const size_t o1 = ((size_t)(b * SS + grow1)) * DD + h * HD;
    #pragma unroll
    for (int dt = 0; dt < 8; dt++) {
        int dc = dt * 8 + tig2;
        float v0 = oacc[dt][0] * inv0, v1 = oacc[dt][1] * inv0;
        float v2 = oacc[dt][2] * inv1, v3 = oacc[dt][3] * inv1;
        __half h0 = __float2half_rn(v0), h1 = __float2half_rn(v1);
        __half h2 = __float2half_rn(v2), h3 = __float2half_rn(v3);
        *(__half2*)&Oh[o0 + dc] = __halves2half2(h0, h1);
        *(__half2*)&Oh[o1 + dc] = __halves2half2(h2, h3);
        *(__half2*)&Ol[o0 + dc] = __halves2half2(
            __float2half_rn(v0 - __half2float(h0)),
            __float2half_rn(v1 - __half2float(h1)));
        *(__half2*)&Ol[o1 + dc] = __halves2half2(
            __float2half_rn(v2 - __half2float(h2)),
            __float2half_rn(v3 - __half2float(h3)));
    }
}

// ---------------------------------------------------------------------------
extern "C" void kernel_launch(void* const* d_in, const int* in_sizes, int n_in,
                              void* d_out, int out_size)
{
    (void)in_sizes; (void)n_in; (void)out_size;
    const float* x  = (const float*)d_in[0];
    const int*   am = (const int*)d_in[1];
    const float* Wq = (const float*)d_in[2];
    const float* bq = (const float*)d_in[3];
    const float* Wk = (const float*)d_in[4];
    const float* bk = (const float*)d_in[5];
    const float* Wv = (const float*)d_in[6];
    const float* bv = (const float*)d_in[7];
    const float* Wp = (const float*)d_in[8];
    const float* bp = (const float*)d_in[9];
    float* out = (float*)d_out;

    __half *xh, *xl, *wh, *ah, *al;
    __half *qh, *ql, *kh, *vh, *vl;
    cudaGetSymbolAddress((void**)&xh, gx_h);
    cudaGetSymbolAddress((void**)&xl, gx_l);
    cudaGetSymbolAddress((void**)&wh, gw_h);
    cudaGetSymbolAddress((void**)&ah, ga_h);
    cudaGetSymbolAddress((void**)&al, ga_l);
    cudaGetSymbolAddress((void**)&qh, gQh);
    cudaGetSymbolAddress((void**)&ql, gQl);
    cudaGetSymbolAddress((void**)&kh, gKh);
    cudaGetSymbolAddress((void**)&vh, gVh);
    cudaGetSymbolAddress((void**)&vl, gVl);

    cudaFuncSetAttribute(tc_gemm_qkv,
                         cudaFuncAttributeMaxDynamicSharedMemorySize, GEMM_SMEM);
    cudaFuncSetAttribute(tc_gemm_out,
                         cudaFuncAttributeMaxDynamicSharedMemorySize, GEMM_SMEM);
    cudaFuncSetAttribute(attn_mma,
                         cudaFuncAttributeMaxDynamicSharedMemorySize, ATT_SMEM);

    const int NX = MM * DD;

    split_f16<<<NX/1024, 256>>>(x, xh, xl, NX);
    conv4_f16<<<dim3(NW/1024, 4), 256>>>(Wq, Wk, Wv, Wp, wh, NW);

    tc_gemm_qkv<<<dim3(24, MM/128), 256, GEMM_SMEM>>>(
        xh, xl, wh, bq, bk, bv, qh, ql, kh, vh, vl);

    attn_mma<<<dim3(SS/128, HH, BB), 256, ATT_SMEM>>>(qh, ql, kh, vh, vl,
                                                      am, ah, al);

    tc_gemm_out<<<dim3(DD/128, MM/128), 256, GEMM_SMEM>>>(
        ah, al, wh + 3*NW, bp, out);
}